// round 1
// baseline (speedup 1.0000x reference)
#include <cuda_runtime.h>

#define NB 16
#define NL 1024
#define ND 768
#define NH 12
#define NDH 64
#define LD (NL*ND)          // 786432
#define NM (NB*NL)          // 16384

// ---------------- scratch (static device globals; no allocation) ----------
__device__ float g_xq[NB*LD];            // gathered q input  (b, l*d)
__device__ float g_xk[NB*LD];            // gathered k input
__device__ float g_q [NB*NH*NL*NDH];     // (b,h,l,dh)
__device__ float g_k [NB*NH*NL*NDH];
__device__ float g_v [NB*NH*NL*NDH];
__device__ float g_o [NB*NL*ND];         // attention output (b,l,inner)

// ---------------- gather: xq[b][i] = x[b][permq[i]] --------------------------
__global__ void __launch_bounds__(256) gather_kernel(
    const float* __restrict__ x,
    const int*   __restrict__ pq,
    const int*   __restrict__ pk)
{
    int b  = blockIdx.y;
    int i4 = (blockIdx.x * 256 + threadIdx.x) * 4;
    const float* xb = x + (size_t)b * LD;

    int q0 = pq[i4+0], q1 = pq[i4+1], q2 = pq[i4+2], q3 = pq[i4+3];
    int k0 = pk[i4+0], k1 = pk[i4+1], k2 = pk[i4+2], k3 = pk[i4+3];

    float4 vq = make_float4(xb[q0], xb[q1], xb[q2], xb[q3]);
    float4 vk = make_float4(xb[k0], xb[k1], xb[k2], xb[k3]);

    *(float4*)&g_xq[(size_t)b*LD + i4] = vq;
    *(float4*)&g_xk[(size_t)b*LD + i4] = vk;
}

// ---------------- SGEMM: C[M=16384,N=768] = A[16384,768] @ W[768,768] --------
// MODE 0: write C in (b,h,l,dh) layout (for q/k/v), no bias
// MODE 1: write C in (m,n) layout with bias (final projection)
template<int MODE>
__global__ void __launch_bounds__(256) sgemm_kernel(
    const float* __restrict__ A,
    const float* __restrict__ W,
    float*       __restrict__ C,
    const float* __restrict__ bias)
{
    __shared__ float As[8][128];   // As[k][m]  (A tile transposed)
    __shared__ float Bs[8][128];   // Bs[k][n]

    int tid = threadIdx.x;
    int m0 = blockIdx.y * 128;
    int n0 = blockIdx.x * 128;
    int ty = tid >> 4, tx = tid & 15;
    int ty4 = ty * 4, tx4 = tx * 4;

    int arow = tid >> 1,  acol = (tid & 1) * 4;   // A tile: 128 rows x 8 k
    int brow = tid >> 5,  bcol = (tid & 31) * 4;  // B tile: 8 rows  x 128 n

    const float* Aptr = A + (size_t)(m0 + arow) * ND + acol;
    const float* Wptr = W + (size_t)brow * ND + n0 + bcol;

    float acc[8][8];
    #pragma unroll
    for (int i = 0; i < 8; i++)
        #pragma unroll
        for (int j = 0; j < 8; j++) acc[i][j] = 0.f;

    for (int k0 = 0; k0 < ND; k0 += 8) {
        float4 av = *(const float4*)(Aptr + k0);
        float4 bv = *(const float4*)(Wptr + (size_t)k0 * ND);

        As[acol+0][arow] = av.x;
        As[acol+1][arow] = av.y;
        As[acol+2][arow] = av.z;
        As[acol+3][arow] = av.w;
        *(float4*)&Bs[brow][bcol] = bv;
        __syncthreads();

        #pragma unroll
        for (int kk = 0; kk < 8; kk++) {
            float ra[8], rb[8];
            *(float4*)&ra[0] = *(float4*)&As[kk][ty4];
            *(float4*)&ra[4] = *(float4*)&As[kk][ty4 + 64];
            *(float4*)&rb[0] = *(float4*)&Bs[kk][tx4];
            *(float4*)&rb[4] = *(float4*)&Bs[kk][tx4 + 64];
            #pragma unroll
            for (int i = 0; i < 8; i++)
                #pragma unroll
                for (int j = 0; j < 8; j++)
                    acc[i][j] += ra[i] * rb[j];
        }
        __syncthreads();
    }

    // epilogue
    #pragma unroll
    for (int i = 0; i < 8; i++) {
        int m = m0 + ((i < 4) ? (ty4 + i) : (64 + ty4 + i - 4));
        #pragma unroll
        for (int half = 0; half < 2; half++) {
            int n = n0 + tx4 + half * 64;
            float4 val = make_float4(acc[i][half*4+0], acc[i][half*4+1],
                                     acc[i][half*4+2], acc[i][half*4+3]);
            if (MODE == 0) {
                int b = m >> 10, l = m & 1023;
                int h = n >> 6,  dh = n & 63;
                *(float4*)&C[((((size_t)b*NH + h)*NL + l) << 6) + dh] = val;
            } else {
                float4 bb = *(const float4*)&bias[n];
                val.x += bb.x; val.y += bb.y; val.z += bb.z; val.w += bb.w;
                *(float4*)&C[(size_t)m * ND + n] = val;
            }
        }
    }
}

// ---------------- flash attention (fp32, online softmax) ---------------------
// grid: (16 q-tiles, 192 bh), block 256 = 16x16 threads, 4x4 micro-tile.
#define SMS 68   // padded row stride (floats); 68*4 bytes keeps float4 alignment

__global__ void __launch_bounds__(256) attn_kernel()
{
    extern __shared__ float sm[];
    float* Qts = sm;                 // [64][SMS]  Q^T  (d, qrow)
    float* Kts = sm + 64*SMS;        // [64][SMS]  K^T  (d, kcol)
    float* Vsm = sm + 2*64*SMS;      // [64][SMS]  V    (kcol, d)
    float* Psm = sm + 3*64*SMS;      // [64][SMS]  P    (qrow, kcol)

    int tid = threadIdx.x;
    int ty = tid >> 4, tx = tid & 15;
    int ty4 = ty * 4, tx4 = tx * 4;

    int bh = blockIdx.y;
    int qt = blockIdx.x;

    const float* Qg = g_q + (size_t)bh * NL * NDH + (size_t)qt * 64 * NDH;
    const float* Kg = g_k + (size_t)bh * NL * NDH;
    const float* Vg = g_v + (size_t)bh * NL * NDH;

    // load Q tile transposed
    for (int idx = tid; idx < 64 * 16; idx += 256) {
        int r = idx >> 4, d4 = (idx & 15) << 2;
        float4 t = *(const float4*)&Qg[r * 64 + d4];
        Qts[(d4+0)*SMS + r] = t.x;
        Qts[(d4+1)*SMS + r] = t.y;
        Qts[(d4+2)*SMS + r] = t.z;
        Qts[(d4+3)*SMS + r] = t.w;
    }
    __syncthreads();

    float mI[4], lI[4], acc[4][4];
    #pragma unroll
    for (int i = 0; i < 4; i++) {
        mI[i] = -1e30f; lI[i] = 0.f;
        #pragma unroll
        for (int j = 0; j < 4; j++) acc[i][j] = 0.f;
    }

    for (int kt = 0; kt < 16; kt++) {
        const float* Kt = Kg + (size_t)kt * 64 * 64;
        const float* Vt = Vg + (size_t)kt * 64 * 64;
        // load K (transposed) and V (natural)
        for (int idx = tid; idx < 64 * 16; idx += 256) {
            int r = idx >> 4, d4 = (idx & 15) << 2;
            float4 t = *(const float4*)&Kt[r * 64 + d4];
            Kts[(d4+0)*SMS + r] = t.x;
            Kts[(d4+1)*SMS + r] = t.y;
            Kts[(d4+2)*SMS + r] = t.z;
            Kts[(d4+3)*SMS + r] = t.w;
            float4 u = *(const float4*)&Vt[r * 64 + d4];
            *(float4*)&Vsm[r * SMS + d4] = u;
        }
        __syncthreads();

        // S = Q @ K^T (each thread 4x4)
        float s[4][4];
        #pragma unroll
        for (int i = 0; i < 4; i++)
            #pragma unroll
            for (int j = 0; j < 4; j++) s[i][j] = 0.f;

        #pragma unroll 8
        for (int d = 0; d < 64; d++) {
            float qa[4], ka[4];
            *(float4*)&qa[0] = *(float4*)&Qts[d * SMS + ty4];
            *(float4*)&ka[0] = *(float4*)&Kts[d * SMS + tx4];
            #pragma unroll
            for (int i = 0; i < 4; i++)
                #pragma unroll
                for (int j = 0; j < 4; j++)
                    s[i][j] += qa[i] * ka[j];
        }

        // online softmax update per row (rows shared across 16-lane groups)
        #pragma unroll
        for (int i = 0; i < 4; i++) {
            float t0 = fmaxf(fmaxf(s[i][0], s[i][1]), fmaxf(s[i][2], s[i][3])) * 0.125f;
            #pragma unroll
            for (int off = 8; off >= 1; off >>= 1)
                t0 = fmaxf(t0, __shfl_xor_sync(0xffffffffu, t0, off, 16));
            float mn   = fmaxf(mI[i], t0);
            float corr = __expf(mI[i] - mn);
            mI[i] = mn;

            float rs = 0.f;
            #pragma unroll
            for (int j = 0; j < 4; j++) {
                float p = __expf(s[i][j] * 0.125f - mn);
                s[i][j] = p;
                rs += p;
            }
            #pragma unroll
            for (int off = 8; off >= 1; off >>= 1)
                rs += __shfl_xor_sync(0xffffffffu, rs, off, 16);
            lI[i] = lI[i] * corr + rs;
            #pragma unroll
            for (int j = 0; j < 4; j++) acc[i][j] *= corr;

            *(float4*)&Psm[(ty4 + i) * SMS + tx4] =
                make_float4(s[i][0], s[i][1], s[i][2], s[i][3]);
        }
        __syncthreads();

        // O += P @ V
        #pragma unroll 4
        for (int kk = 0; kk < 64; kk += 4) {
            float vr[4][4];
            #pragma unroll
            for (int t = 0; t < 4; t++)
                *(float4*)&vr[t][0] = *(float4*)&Vsm[(kk + t) * SMS + tx4];
            #pragma unroll
            for (int i = 0; i < 4; i++) {
                float pr[4];
                *(float4*)&pr[0] = *(float4*)&Psm[(ty4 + i) * SMS + kk];
                #pragma unroll
                for (int j = 0; j < 4; j++)
                    acc[i][j] += pr[0]*vr[0][j] + pr[1]*vr[1][j]
                               + pr[2]*vr[2][j] + pr[3]*vr[3][j];
            }
        }
        __syncthreads();
    }

    // epilogue: normalize and write to (b, l, h*64+dh)
    int b = bh / NH, h = bh % NH;
    float* Og = g_o + ((size_t)(b * NL) + qt * 64) * ND + h * 64;
    #pragma unroll
    for (int i = 0; i < 4; i++) {
        float inv = 1.f / lI[i];
        *(float4*)&Og[(size_t)(ty4 + i) * ND + tx4] =
            make_float4(acc[i][0]*inv, acc[i][1]*inv, acc[i][2]*inv, acc[i][3]*inv);
    }
}

// ---------------- launch --------------------------------------------------
extern "C" void kernel_launch(void* const* d_in, const int* in_sizes, int n_in,
                              void* d_out, int out_size)
{
    const float* x  = (const float*)d_in[0];
    const float* Wq = (const float*)d_in[1];
    const float* Wk = (const float*)d_in[2];
    const float* Wv = (const float*)d_in[3];
    const float* Wo = (const float*)d_in[4];
    const float* bo = (const float*)d_in[5];
    const int*   pq = (const int*)d_in[6];
    const int*   pk = (const int*)d_in[7];
    float* out = (float*)d_out;

    float *xq, *xk, *q, *k, *v, *o;
    cudaGetSymbolAddress((void**)&xq, g_xq);
    cudaGetSymbolAddress((void**)&xk, g_xk);
    cudaGetSymbolAddress((void**)&q,  g_q);
    cudaGetSymbolAddress((void**)&k,  g_k);
    cudaGetSymbolAddress((void**)&v,  g_v);
    cudaGetSymbolAddress((void**)&o,  g_o);

    const int ATTN_SMEM = 4 * 64 * SMS * (int)sizeof(float);  // 69632 B
    cudaFuncSetAttribute(attn_kernel,
                         cudaFuncAttributeMaxDynamicSharedMemorySize, ATTN_SMEM);

    // 1. gathers
    gather_kernel<<<dim3(LD / 1024, NB), 256>>>(x, pq, pk);

    // 2. q/k/v projections
    dim3 gg(ND / 128, NM / 128);   // (6, 128)
    sgemm_kernel<0><<<gg, 256>>>(xq, Wq, q, nullptr);
    sgemm_kernel<0><<<gg, 256>>>(xk, Wk, k, nullptr);
    sgemm_kernel<0><<<gg, 256>>>(x,  Wv, v, nullptr);

    // 3. attention
    attn_kernel<<<dim3(NL / 64, NB * NH), 256, ATTN_SMEM>>>();

    // 4. output projection + bias
    sgemm_kernel<1><<<gg, 256>>>(o, Wo, out, bo);
}

// round 3
// speedup vs baseline: 1.4706x; 1.4706x over previous
#include <cuda_runtime.h>
#include <cstdint>

#define NB 16
#define NL 1024
#define ND 768
#define NH 12
#define NDH 64
#define LD (NL*ND)          // 786432
#define NM (NB*NL)          // 16384

// ---------------- scratch (static device globals; no allocation) ----------
__device__ float g_xq[NB*LD];            // gathered q input  (b, l*d)
__device__ float g_xk[NB*LD];            // gathered k input
__device__ float g_q [NM*ND];            // (b,h,l,dh)
__device__ float g_k [NM*ND];
__device__ float g_v [NM*ND];
__device__ float g_o [NM*ND];            // attention output (b,l,inner)
__device__ float g_WT[4*ND*ND];          // transposed weights [n][k]

// ---------------- helpers ---------------------------------------------------
__device__ __forceinline__ uint32_t f2tf32(float f) {
    uint32_t r;
    asm("cvt.rna.tf32.f32 %0, %1;" : "=r"(r) : "f"(f));
    return r;
}

__device__ __forceinline__ void mma_tf32(float c[4], const uint32_t a[4],
                                         const uint32_t b[2]) {
    asm volatile(
        "mma.sync.aligned.m16n8k8.row.col.f32.tf32.tf32.f32 "
        "{%0,%1,%2,%3}, {%4,%5,%6,%7}, {%8,%9}, {%0,%1,%2,%3};"
        : "+f"(c[0]), "+f"(c[1]), "+f"(c[2]), "+f"(c[3])
        : "r"(a[0]), "r"(a[1]), "r"(a[2]), "r"(a[3]), "r"(b[0]), "r"(b[1]));
}

// ---------------- weight transpose: g_WT[z][n][k] = W_z[k][n] ---------------
__global__ void __launch_bounds__(256) transpose_kernel(
    const float* __restrict__ Wq, const float* __restrict__ Wk,
    const float* __restrict__ Wv, const float* __restrict__ Wo)
{
    __shared__ float t[32][33];
    const float* src = (blockIdx.z == 0) ? Wq : (blockIdx.z == 1) ? Wk
                     : (blockIdx.z == 2) ? Wv : Wo;
    float* dst = g_WT + (size_t)blockIdx.z * ND * ND;
    int x0 = blockIdx.x * 32, y0 = blockIdx.y * 32;
    int tx = threadIdx.x, ty = threadIdx.y;          // 32 x 8
    #pragma unroll
    for (int j = 0; j < 32; j += 8)
        t[ty + j][tx] = src[(size_t)(y0 + ty + j) * ND + x0 + tx];
    __syncthreads();
    #pragma unroll
    for (int j = 0; j < 32; j += 8)
        dst[(size_t)(x0 + ty + j) * ND + y0 + tx] = t[tx][ty + j];
}

// ---------------- gather: xq[b][i] = x[b][permq[i]] -------------------------
__global__ void __launch_bounds__(256) gather_kernel(
    const float* __restrict__ x,
    const int*   __restrict__ pq,
    const int*   __restrict__ pk)
{
    int b  = blockIdx.y;
    int i4 = (blockIdx.x * 256 + threadIdx.x) * 4;
    const float* xb = x + (size_t)b * LD;

    int q0 = pq[i4+0], q1 = pq[i4+1], q2 = pq[i4+2], q3 = pq[i4+3];
    int k0 = pk[i4+0], k1 = pk[i4+1], k2 = pk[i4+2], k3 = pk[i4+3];

    float4 vq = make_float4(xb[q0], xb[q1], xb[q2], xb[q3]);
    float4 vk = make_float4(xb[k0], xb[k1], xb[k2], xb[k3]);

    *(float4*)&g_xq[(size_t)b*LD + i4] = vq;
    *(float4*)&g_xk[(size_t)b*LD + i4] = vk;
}

// ---------------- tf32 tensor-core GEMM -------------------------------------
// C[16384,768] = A[16384,768] @ W[768,768]; BT = W^T in [n][k] layout.
// CTA: 128 threads (4 warps, 2m x 2n), tile BM=128 BN=128 BK=32.
// Warp tile 64x64 = 4 m-frags(16) x 8 n-frags(8), mma m16n8k8 tf32.
// MODE 0: scatter C to (b,h,l,dh), no bias.  MODE 1: row-major + bias.
#define AS_STRIDE 36

template<int MODE>
__global__ void __launch_bounds__(128) gemm_mma(
    const float* __restrict__ A,
    const float* __restrict__ BT,
    float*       __restrict__ C,
    const float* __restrict__ bias)
{
    __shared__ uint32_t As[128][AS_STRIDE];   // [m][k] tf32
    __shared__ uint32_t Bs[128][AS_STRIDE];   // [n][k] tf32

    int tid  = threadIdx.x;
    int lane = tid & 31, wid = tid >> 5;
    int wm = wid >> 1, wn = wid & 1;          // warp position 2x2
    int g = lane >> 2, t = lane & 3;
    int m0 = blockIdx.y * 128, n0 = blockIdx.x * 128;

    int lr = tid >> 3;          // 0..15  (row group for loads)
    int lc = tid & 7;           // 0..7   (float4 column)

    float c[4][8][4];
    #pragma unroll
    for (int mt = 0; mt < 4; mt++)
        #pragma unroll
        for (int nt = 0; nt < 8; nt++)
            #pragma unroll
            for (int i = 0; i < 4; i++) c[mt][nt][i] = 0.f;

    const float* Ap = A  + (size_t)m0 * ND;
    const float* Bp = BT + (size_t)n0 * ND;

    for (int kt = 0; kt < ND / 32; kt++) {
        // load A tile [128m x 32k] coalesced (8 lanes per row), cvt to tf32
        #pragma unroll
        for (int it = 0; it < 8; it++) {
            int r = it * 16 + lr;
            float4 va = *(const float4*)&Ap[(size_t)r * ND + kt * 32 + lc * 4];
            uint4 ua = make_uint4(f2tf32(va.x), f2tf32(va.y),
                                  f2tf32(va.z), f2tf32(va.w));
            *(uint4*)&As[r][lc * 4] = ua;
            float4 vb = *(const float4*)&Bp[(size_t)r * ND + kt * 32 + lc * 4];
            uint4 ub = make_uint4(f2tf32(vb.x), f2tf32(vb.y),
                                  f2tf32(vb.z), f2tf32(vb.w));
            *(uint4*)&Bs[r][lc * 4] = ub;
        }
        __syncthreads();

        #pragma unroll
        for (int kk = 0; kk < 4; kk++) {
            uint32_t a[4][4], b[8][2];
            int k0 = kk * 8 + t;
            #pragma unroll
            for (int mt = 0; mt < 4; mt++) {
                int mr = wm * 64 + mt * 16 + g;
                a[mt][0] = As[mr][k0];
                a[mt][1] = As[mr + 8][k0];
                a[mt][2] = As[mr][k0 + 4];
                a[mt][3] = As[mr + 8][k0 + 4];
            }
            #pragma unroll
            for (int nt = 0; nt < 8; nt++) {
                int nr = wn * 64 + nt * 8 + g;
                b[nt][0] = Bs[nr][k0];
                b[nt][1] = Bs[nr][k0 + 4];
            }
            #pragma unroll
            for (int mt = 0; mt < 4; mt++)
                #pragma unroll
                for (int nt = 0; nt < 8; nt++)
                    mma_tf32(c[mt][nt], a[mt], b[nt]);
        }
        __syncthreads();
    }

    // epilogue
    #pragma unroll
    for (int mt = 0; mt < 4; mt++) {
        int m = m0 + wm * 64 + mt * 16 + g;
        #pragma unroll
        for (int nt = 0; nt < 8; nt++) {
            int n = n0 + wn * 64 + nt * 8 + 2 * t;
            if (MODE == 0) {
                int b0i = m >> 10, l = m & 1023;
                int h = n >> 6, dh = n & 63;
                size_t base0 = ((((size_t)b0i * NH + h) * NL + l) << 6) + dh;
                size_t base1 = ((((size_t)b0i * NH + h) * NL + (l)) << 6) + dh;
                *(float2*)&C[base0] = make_float2(c[mt][nt][0], c[mt][nt][1]);
                // row m+8 (same b, l+8 only if within; m+8 keeps same b since tiles are 16-row aligned within 1024)
                int m2 = m + 8;
                int l2 = m2 & 1023;
                size_t base2 = ((((size_t)b0i * NH + h) * NL + l2) << 6) + dh;
                *(float2*)&C[base2] = make_float2(c[mt][nt][2], c[mt][nt][3]);
                (void)base1;
            } else {
                float2 bb = *(const float2*)&bias[n];
                *(float2*)&C[(size_t)m * ND + n] =
                    make_float2(c[mt][nt][0] + bb.x, c[mt][nt][1] + bb.y);
                *(float2*)&C[(size_t)(m + 8) * ND + n] =
                    make_float2(c[mt][nt][2] + bb.x, c[mt][nt][3] + bb.y);
            }
        }
    }
}

// ---------------- flash attention (fp32, online softmax) --------------------
#define SMS 68

__global__ void __launch_bounds__(256) attn_kernel()
{
    extern __shared__ float sm[];
    float* Qts = sm;                 // [64][SMS]  Q^T
    float* Kts = sm + 64*SMS;        // [64][SMS]  K^T
    float* Vsm = sm + 2*64*SMS;      // [64][SMS]  V
    float* Psm = sm + 3*64*SMS;      // [64][SMS]  P

    int tid = threadIdx.x;
    int ty = tid >> 4, tx = tid & 15;
    int ty4 = ty * 4, tx4 = tx * 4;

    int bh = blockIdx.y;
    int qt = blockIdx.x;

    const float* Qg = g_q + (size_t)bh * NL * NDH + (size_t)qt * 64 * NDH;
    const float* Kg = g_k + (size_t)bh * NL * NDH;
    const float* Vg = g_v + (size_t)bh * NL * NDH;

    for (int idx = tid; idx < 64 * 16; idx += 256) {
        int r = idx >> 4, d4 = (idx & 15) << 2;
        float4 t = *(const float4*)&Qg[r * 64 + d4];
        Qts[(d4+0)*SMS + r] = t.x;
        Qts[(d4+1)*SMS + r] = t.y;
        Qts[(d4+2)*SMS + r] = t.z;
        Qts[(d4+3)*SMS + r] = t.w;
    }
    __syncthreads();

    float mI[4], lI[4], acc[4][4];
    #pragma unroll
    for (int i = 0; i < 4; i++) {
        mI[i] = -1e30f; lI[i] = 0.f;
        #pragma unroll
        for (int j = 0; j < 4; j++) acc[i][j] = 0.f;
    }

    for (int kt = 0; kt < 16; kt++) {
        const float* Kt = Kg + (size_t)kt * 64 * 64;
        const float* Vt = Vg + (size_t)kt * 64 * 64;
        for (int idx = tid; idx < 64 * 16; idx += 256) {
            int r = idx >> 4, d4 = (idx & 15) << 2;
            float4 t = *(const float4*)&Kt[r * 64 + d4];
            Kts[(d4+0)*SMS + r] = t.x;
            Kts[(d4+1)*SMS + r] = t.y;
            Kts[(d4+2)*SMS + r] = t.z;
            Kts[(d4+3)*SMS + r] = t.w;
            float4 u = *(const float4*)&Vt[r * 64 + d4];
            *(float4*)&Vsm[r * SMS + d4] = u;
        }
        __syncthreads();

        float s[4][4];
        #pragma unroll
        for (int i = 0; i < 4; i++)
            #pragma unroll
            for (int j = 0; j < 4; j++) s[i][j] = 0.f;

        #pragma unroll 8
        for (int d = 0; d < 64; d++) {
            float qa[4], ka[4];
            *(float4*)&qa[0] = *(float4*)&Qts[d * SMS + ty4];
            *(float4*)&ka[0] = *(float4*)&Kts[d * SMS + tx4];
            #pragma unroll
            for (int i = 0; i < 4; i++)
                #pragma unroll
                for (int j = 0; j < 4; j++)
                    s[i][j] += qa[i] * ka[j];
        }

        #pragma unroll
        for (int i = 0; i < 4; i++) {
            float t0 = fmaxf(fmaxf(s[i][0], s[i][1]), fmaxf(s[i][2], s[i][3])) * 0.125f;
            #pragma unroll
            for (int off = 8; off >= 1; off >>= 1)
                t0 = fmaxf(t0, __shfl_xor_sync(0xffffffffu, t0, off, 16));
            float mn   = fmaxf(mI[i], t0);
            float corr = __expf(mI[i] - mn);
            mI[i] = mn;

            float rs = 0.f;
            #pragma unroll
            for (int j = 0; j < 4; j++) {
                float p = __expf(s[i][j] * 0.125f - mn);
                s[i][j] = p;
                rs += p;
            }
            #pragma unroll
            for (int off = 8; off >= 1; off >>= 1)
                rs += __shfl_xor_sync(0xffffffffu, rs, off, 16);
            lI[i] = lI[i] * corr + rs;
            #pragma unroll
            for (int j = 0; j < 4; j++) acc[i][j] *= corr;

            *(float4*)&Psm[(ty4 + i) * SMS + tx4] =
                make_float4(s[i][0], s[i][1], s[i][2], s[i][3]);
        }
        __syncthreads();

        #pragma unroll 4
        for (int kk = 0; kk < 64; kk += 4) {
            float vr[4][4];
            #pragma unroll
            for (int t = 0; t < 4; t++)
                *(float4*)&vr[t][0] = *(float4*)&Vsm[(kk + t) * SMS + tx4];
            #pragma unroll
            for (int i = 0; i < 4; i++) {
                float pr[4];
                *(float4*)&pr[0] = *(float4*)&Psm[(ty4 + i) * SMS + kk];
                #pragma unroll
                for (int j = 0; j < 4; j++)
                    acc[i][j] += pr[0]*vr[0][j] + pr[1]*vr[1][j]
                               + pr[2]*vr[2][j] + pr[3]*vr[3][j];
            }
        }
        __syncthreads();
    }

    int b = bh / NH, h = bh % NH;
    float* Og = g_o + ((size_t)(b * NL) + qt * 64) * ND + h * 64;
    #pragma unroll
    for (int i = 0; i < 4; i++) {
        float inv = 1.f / lI[i];
        *(float4*)&Og[(size_t)(ty4 + i) * ND + tx4] =
            make_float4(acc[i][0]*inv, acc[i][1]*inv, acc[i][2]*inv, acc[i][3]*inv);
    }
}

// ---------------- launch -----------------------------------------------------
extern "C" void kernel_launch(void* const* d_in, const int* in_sizes, int n_in,
                              void* d_out, int out_size)
{
    const float* x  = (const float*)d_in[0];
    const float* Wq = (const float*)d_in[1];
    const float* Wk = (const float*)d_in[2];
    const float* Wv = (const float*)d_in[3];
    const float* Wo = (const float*)d_in[4];
    const float* bo = (const float*)d_in[5];
    const int*   pq = (const int*)d_in[6];
    const int*   pk = (const int*)d_in[7];
    float* out = (float*)d_out;

    float *xq, *xk, *q, *k, *v, *o, *wt;
    cudaGetSymbolAddress((void**)&xq, g_xq);
    cudaGetSymbolAddress((void**)&xk, g_xk);
    cudaGetSymbolAddress((void**)&q,  g_q);
    cudaGetSymbolAddress((void**)&k,  g_k);
    cudaGetSymbolAddress((void**)&v,  g_v);
    cudaGetSymbolAddress((void**)&o,  g_o);
    cudaGetSymbolAddress((void**)&wt, g_WT);

    const int ATTN_SMEM = 4 * 64 * SMS * (int)sizeof(float);  // 69632 B
    cudaFuncSetAttribute(attn_kernel,
                         cudaFuncAttributeMaxDynamicSharedMemorySize, ATTN_SMEM);

    // 0. weight transposes (W[k][n] -> WT[n][k])
    transpose_kernel<<<dim3(24, 24, 4), dim3(32, 8)>>>(Wq, Wk, Wv, Wo);

    // 1. gathers
    gather_kernel<<<dim3(LD / 1024, NB), 256>>>(x, pq, pk);

    // 2. q/k/v projections (tf32 mma.sync)
    dim3 gg(ND / 128, NM / 128);   // (6, 128)
    gemm_mma<0><<<gg, 128>>>(xq, wt + 0*(size_t)ND*ND, q, nullptr);
    gemm_mma<0><<<gg, 128>>>(xk, wt + 1*(size_t)ND*ND, k, nullptr);
    gemm_mma<0><<<gg, 128>>>(x,  wt + 2*(size_t)ND*ND, v, nullptr);

    // 3. attention
    attn_kernel<<<dim3(NL / 64, NB * NH), 256, ATTN_SMEM>>>();

    // 4. output projection + bias (tf32 mma.sync)
    gemm_mma<1><<<gg, 128>>>(o, wt + 3*(size_t)ND*ND, out, bo);
}

// round 4
// speedup vs baseline: 2.6716x; 1.8166x over previous
#include <cuda_runtime.h>
#include <cstdint>

#define NB 16
#define NL 1024
#define ND 768
#define NH 12
#define NDH 64
#define LD (NL*ND)          // 786432
#define NM (NB*NL)          // 16384

// ---------------- scratch (static device globals; no allocation) ----------
__device__ float g_xq[NB*LD];            // gathered q input  (b, l*d)
__device__ float g_xk[NB*LD];            // gathered k input
__device__ float g_q [NM*ND];            // (b,h,l,dh)
__device__ float g_k [NM*ND];            // (b,h,l,dh)
__device__ float g_v [NM*ND];            // V^T: (b,h,dh,l)
__device__ float g_o [NM*ND];            // attention output (b,l,inner)
__device__ float g_WT[4*ND*ND];          // transposed weights [n][k]

// ---------------- helpers ---------------------------------------------------
__device__ __forceinline__ uint32_t f2tf32(float f) {
    uint32_t r;
    asm("cvt.rna.tf32.f32 %0, %1;" : "=r"(r) : "f"(f));
    return r;
}

__device__ __forceinline__ void mma_tf32(float c[4], const uint32_t a[4],
                                         const uint32_t b[2]) {
    asm volatile(
        "mma.sync.aligned.m16n8k8.row.col.f32.tf32.tf32.f32 "
        "{%0,%1,%2,%3}, {%4,%5,%6,%7}, {%8,%9}, {%0,%1,%2,%3};"
        : "+f"(c[0]), "+f"(c[1]), "+f"(c[2]), "+f"(c[3])
        : "r"(a[0]), "r"(a[1]), "r"(a[2]), "r"(a[3]), "r"(b[0]), "r"(b[1]));
}

// ---------------- weight transpose: g_WT[z][n][k] = W_z[k][n] ---------------
__global__ void __launch_bounds__(256) transpose_kernel(
    const float* __restrict__ Wq, const float* __restrict__ Wk,
    const float* __restrict__ Wv, const float* __restrict__ Wo)
{
    __shared__ float t[32][33];
    const float* src = (blockIdx.z == 0) ? Wq : (blockIdx.z == 1) ? Wk
                     : (blockIdx.z == 2) ? Wv : Wo;
    float* dst = g_WT + (size_t)blockIdx.z * ND * ND;
    int x0 = blockIdx.x * 32, y0 = blockIdx.y * 32;
    int tx = threadIdx.x, ty = threadIdx.y;          // 32 x 8
    #pragma unroll
    for (int j = 0; j < 32; j += 8)
        t[ty + j][tx] = src[(size_t)(y0 + ty + j) * ND + x0 + tx];
    __syncthreads();
    #pragma unroll
    for (int j = 0; j < 32; j += 8)
        dst[(size_t)(x0 + ty + j) * ND + y0 + tx] = t[tx][ty + j];
}

// ---------------- gather: xq[b][i] = x[b][permq[i]] -------------------------
__global__ void __launch_bounds__(256) gather_kernel(
    const float* __restrict__ x,
    const int*   __restrict__ pq,
    const int*   __restrict__ pk)
{
    int b  = blockIdx.y;
    int i4 = (blockIdx.x * 256 + threadIdx.x) * 4;
    const float* xb = x + (size_t)b * LD;

    int q0 = pq[i4+0], q1 = pq[i4+1], q2 = pq[i4+2], q3 = pq[i4+3];
    int k0 = pk[i4+0], k1 = pk[i4+1], k2 = pk[i4+2], k3 = pk[i4+3];

    float4 vq = make_float4(xb[q0], xb[q1], xb[q2], xb[q3]);
    float4 vk = make_float4(xb[k0], xb[k1], xb[k2], xb[k3]);

    *(float4*)&g_xq[(size_t)b*LD + i4] = vq;
    *(float4*)&g_xk[(size_t)b*LD + i4] = vk;
}

// ---------------- tf32 tensor-core GEMM -------------------------------------
// C[16384,768] = A[16384,768] @ W[768,768]; BT = W^T in [n][k] layout.
// MODE 0: scatter C to (b,h,l,dh).  MODE 1: row-major + bias.
// MODE 2: scatter C to V^T layout (b,h,dh,l).
#define AS_STRIDE 36

template<int MODE>
__global__ void __launch_bounds__(128) gemm_mma(
    const float* __restrict__ A,
    const float* __restrict__ BT,
    float*       __restrict__ C,
    const float* __restrict__ bias)
{
    __shared__ uint32_t As[128][AS_STRIDE];   // [m][k] tf32
    __shared__ uint32_t Bs[128][AS_STRIDE];   // [n][k] tf32

    int tid  = threadIdx.x;
    int lane = tid & 31, wid = tid >> 5;
    int wm = wid >> 1, wn = wid & 1;          // warp position 2x2
    int g = lane >> 2, t = lane & 3;
    int m0 = blockIdx.y * 128, n0 = blockIdx.x * 128;

    int lr = tid >> 3;          // 0..15
    int lc = tid & 7;           // 0..7

    float c[4][8][4];
    #pragma unroll
    for (int mt = 0; mt < 4; mt++)
        #pragma unroll
        for (int nt = 0; nt < 8; nt++)
            #pragma unroll
            for (int i = 0; i < 4; i++) c[mt][nt][i] = 0.f;

    const float* Ap = A  + (size_t)m0 * ND;
    const float* Bp = BT + (size_t)n0 * ND;

    for (int kt = 0; kt < ND / 32; kt++) {
        #pragma unroll
        for (int it = 0; it < 8; it++) {
            int r = it * 16 + lr;
            float4 va = *(const float4*)&Ap[(size_t)r * ND + kt * 32 + lc * 4];
            uint4 ua = make_uint4(f2tf32(va.x), f2tf32(va.y),
                                  f2tf32(va.z), f2tf32(va.w));
            *(uint4*)&As[r][lc * 4] = ua;
            float4 vb = *(const float4*)&Bp[(size_t)r * ND + kt * 32 + lc * 4];
            uint4 ub = make_uint4(f2tf32(vb.x), f2tf32(vb.y),
                                  f2tf32(vb.z), f2tf32(vb.w));
            *(uint4*)&Bs[r][lc * 4] = ub;
        }
        __syncthreads();

        #pragma unroll
        for (int kk = 0; kk < 4; kk++) {
            uint32_t a[4][4], b[8][2];
            int k0 = kk * 8 + t;
            #pragma unroll
            for (int mt = 0; mt < 4; mt++) {
                int mr = wm * 64 + mt * 16 + g;
                a[mt][0] = As[mr][k0];
                a[mt][1] = As[mr + 8][k0];
                a[mt][2] = As[mr][k0 + 4];
                a[mt][3] = As[mr + 8][k0 + 4];
            }
            #pragma unroll
            for (int nt = 0; nt < 8; nt++) {
                int nr = wn * 64 + nt * 8 + g;
                b[nt][0] = Bs[nr][k0];
                b[nt][1] = Bs[nr][k0 + 4];
            }
            #pragma unroll
            for (int mt = 0; mt < 4; mt++)
                #pragma unroll
                for (int nt = 0; nt < 8; nt++)
                    mma_tf32(c[mt][nt], a[mt], b[nt]);
        }
        __syncthreads();
    }

    // epilogue
    #pragma unroll
    for (int mt = 0; mt < 4; mt++) {
        int m = m0 + wm * 64 + mt * 16 + g;
        #pragma unroll
        for (int nt = 0; nt < 8; nt++) {
            int n = n0 + wn * 64 + nt * 8 + 2 * t;
            if (MODE == 0) {
                int b0i = m >> 10, l = m & 1023;
                int h = n >> 6, dh = n & 63;
                size_t base0 = ((((size_t)b0i * NH + h) * NL + l) << 6) + dh;
                *(float2*)&C[base0] = make_float2(c[mt][nt][0], c[mt][nt][1]);
                size_t base2 = ((((size_t)b0i * NH + h) * NL + (l + 8)) << 6) + dh;
                *(float2*)&C[base2] = make_float2(c[mt][nt][2], c[mt][nt][3]);
            } else if (MODE == 2) {
                int b0i = m >> 10, l = m & 1023;
                int h = n >> 6, dh = n & 63;
                size_t base = (((size_t)b0i * NH + h) * NDH + dh) * NL + l;
                C[base]          = c[mt][nt][0];
                C[base + NL]     = c[mt][nt][1];
                C[base + 8]      = c[mt][nt][2];
                C[base + NL + 8] = c[mt][nt][3];
            } else {
                float2 bb = *(const float2*)&bias[n];
                *(float2*)&C[(size_t)m * ND + n] =
                    make_float2(c[mt][nt][0] + bb.x, c[mt][nt][1] + bb.y);
                *(float2*)&C[(size_t)(m + 8) * ND + n] =
                    make_float2(c[mt][nt][2] + bb.x, c[mt][nt][3] + bb.y);
            }
        }
    }
}

// ---------------- tensor-core flash attention (tf32 mma) --------------------
// grid (16 q-tiles, 192 bh), block 128 (4 warps x 16 rows).
// K in (b,h,l,dh) is natively [n=kv][k=d]; V^T in (b,h,dh,l) is [n=dh][k=kv].
#define ASTR2 68

__global__ void __launch_bounds__(128) attn_mma_kernel()
{
    extern __shared__ uint32_t smu[];
    uint32_t (*Ks)[ASTR2] = (uint32_t(*)[ASTR2])smu;               // K tile [kv][d] (Q staging first)
    uint32_t (*Vs)[ASTR2] = (uint32_t(*)[ASTR2])(smu + 64*ASTR2);  // V^T [dh][kv]
    uint32_t (*Ps)[ASTR2] = (uint32_t(*)[ASTR2])(smu + 2*64*ASTR2);// P [qrow][kv]

    int tid = threadIdx.x, lane = tid & 31, wid = tid >> 5;
    int g = lane >> 2, t = lane & 3;
    int bh = blockIdx.y, qt = blockIdx.x;
    int mrow = wid * 16 + g;

    const float* Qg  = g_q + (size_t)bh * NL * NDH + (size_t)qt * 64 * NDH;
    const float* Kg  = g_k + (size_t)bh * NL * NDH;
    const float* VTg = g_v + (size_t)bh * NDH * NL;

    // stage Q into Ks, pull fragments to registers
    #pragma unroll
    for (int it = 0; it < 8; it++) {
        int idx = it * 128 + tid;
        int r = idx >> 4, c4 = (idx & 15) << 2;
        float4 v = *(const float4*)&Qg[r * 64 + c4];
        Ks[r][c4+0] = f2tf32(v.x); Ks[r][c4+1] = f2tf32(v.y);
        Ks[r][c4+2] = f2tf32(v.z); Ks[r][c4+3] = f2tf32(v.w);
    }
    __syncthreads();
    uint32_t aq[8][4];
    #pragma unroll
    for (int kk = 0; kk < 8; kk++) {
        aq[kk][0] = Ks[mrow][kk*8 + t];
        aq[kk][1] = Ks[mrow + 8][kk*8 + t];
        aq[kk][2] = Ks[mrow][kk*8 + t + 4];
        aq[kk][3] = Ks[mrow + 8][kk*8 + t + 4];
    }

    float mI0 = -1e30f, mI1 = -1e30f, lI0 = 0.f, lI1 = 0.f;
    float o[8][4];
    #pragma unroll
    for (int nt = 0; nt < 8; nt++)
        #pragma unroll
        for (int i = 0; i < 4; i++) o[nt][i] = 0.f;

    for (int kt = 0; kt < 16; kt++) {
        __syncthreads();   // previous iter readers done before overwrite
        const float* Kt = Kg + (size_t)kt * 64 * 64;
        #pragma unroll
        for (int it = 0; it < 8; it++) {
            int idx = it * 128 + tid;
            int r = idx >> 4, c4 = (idx & 15) << 2;
            float4 v = *(const float4*)&Kt[r * 64 + c4];
            Ks[r][c4+0] = f2tf32(v.x); Ks[r][c4+1] = f2tf32(v.y);
            Ks[r][c4+2] = f2tf32(v.z); Ks[r][c4+3] = f2tf32(v.w);
            float4 u = *(const float4*)&VTg[(size_t)r * NL + kt * 64 + c4];
            Vs[r][c4+0] = f2tf32(u.x); Vs[r][c4+1] = f2tf32(u.y);
            Vs[r][c4+2] = f2tf32(u.z); Vs[r][c4+3] = f2tf32(u.w);
        }
        __syncthreads();

        // S = Q @ K^T
        float s[8][4];
        #pragma unroll
        for (int nt = 0; nt < 8; nt++)
            #pragma unroll
            for (int i = 0; i < 4; i++) s[nt][i] = 0.f;
        #pragma unroll
        for (int kk = 0; kk < 8; kk++) {
            #pragma unroll
            for (int nt = 0; nt < 8; nt++) {
                uint32_t b[2];
                int nr = nt * 8 + g;
                b[0] = Ks[nr][kk*8 + t];
                b[1] = Ks[nr][kk*8 + t + 4];
                mma_tf32(s[nt], aq[kk], b);
            }
        }
        #pragma unroll
        for (int nt = 0; nt < 8; nt++)
            #pragma unroll
            for (int i = 0; i < 4; i++) s[nt][i] *= 0.125f;

        // online softmax: rows g (regs 0,1) and g+8 (regs 2,3)
        float mx0 = -1e30f, mx1 = -1e30f;
        #pragma unroll
        for (int nt = 0; nt < 8; nt++) {
            mx0 = fmaxf(mx0, fmaxf(s[nt][0], s[nt][1]));
            mx1 = fmaxf(mx1, fmaxf(s[nt][2], s[nt][3]));
        }
        mx0 = fmaxf(mx0, __shfl_xor_sync(0xffffffffu, mx0, 1));
        mx0 = fmaxf(mx0, __shfl_xor_sync(0xffffffffu, mx0, 2));
        mx1 = fmaxf(mx1, __shfl_xor_sync(0xffffffffu, mx1, 1));
        mx1 = fmaxf(mx1, __shfl_xor_sync(0xffffffffu, mx1, 2));

        float mn0 = fmaxf(mI0, mx0), mn1 = fmaxf(mI1, mx1);
        float corr0 = __expf(mI0 - mn0), corr1 = __expf(mI1 - mn1);
        mI0 = mn0; mI1 = mn1;

        float sum0 = 0.f, sum1 = 0.f;
        #pragma unroll
        for (int nt = 0; nt < 8; nt++) {
            float p0 = __expf(s[nt][0] - mn0);
            float p1 = __expf(s[nt][1] - mn0);
            float p2 = __expf(s[nt][2] - mn1);
            float p3 = __expf(s[nt][3] - mn1);
            sum0 += p0 + p1; sum1 += p2 + p3;
            int col = nt * 8 + 2 * t;
            *(uint2*)&Ps[mrow][col]     = make_uint2(f2tf32(p0), f2tf32(p1));
            *(uint2*)&Ps[mrow + 8][col] = make_uint2(f2tf32(p2), f2tf32(p3));
        }
        sum0 += __shfl_xor_sync(0xffffffffu, sum0, 1);
        sum0 += __shfl_xor_sync(0xffffffffu, sum0, 2);
        sum1 += __shfl_xor_sync(0xffffffffu, sum1, 1);
        sum1 += __shfl_xor_sync(0xffffffffu, sum1, 2);
        lI0 = lI0 * corr0 + sum0;
        lI1 = lI1 * corr1 + sum1;

        #pragma unroll
        for (int nt = 0; nt < 8; nt++) {
            o[nt][0] *= corr0; o[nt][1] *= corr0;
            o[nt][2] *= corr1; o[nt][3] *= corr1;
        }
        __syncwarp();

        // O += P @ V   (A = P from smem, B = V^T tile)
        #pragma unroll
        for (int kk = 0; kk < 8; kk++) {
            uint32_t ap[4];
            ap[0] = Ps[mrow][kk*8 + t];
            ap[1] = Ps[mrow + 8][kk*8 + t];
            ap[2] = Ps[mrow][kk*8 + t + 4];
            ap[3] = Ps[mrow + 8][kk*8 + t + 4];
            #pragma unroll
            for (int nt = 0; nt < 8; nt++) {
                uint32_t b[2];
                int nr = nt * 8 + g;
                b[0] = Vs[nr][kk*8 + t];
                b[1] = Vs[nr][kk*8 + t + 4];
                mma_tf32(o[nt], ap, b);
            }
        }
    }

    // epilogue
    float inv0 = 1.f / lI0, inv1 = 1.f / lI1;
    int b = bh / NH, h = bh % NH;
    float* Og = g_o + ((size_t)b * NL + qt * 64) * ND + h * 64;
    #pragma unroll
    for (int nt = 0; nt < 8; nt++) {
        int col = nt * 8 + 2 * t;
        *(float2*)&Og[(size_t)mrow * ND + col] =
            make_float2(o[nt][0] * inv0, o[nt][1] * inv0);
        *(float2*)&Og[(size_t)(mrow + 8) * ND + col] =
            make_float2(o[nt][2] * inv1, o[nt][3] * inv1);
    }
}

// ---------------- launch -----------------------------------------------------
extern "C" void kernel_launch(void* const* d_in, const int* in_sizes, int n_in,
                              void* d_out, int out_size)
{
    const float* x  = (const float*)d_in[0];
    const float* Wq = (const float*)d_in[1];
    const float* Wk = (const float*)d_in[2];
    const float* Wv = (const float*)d_in[3];
    const float* Wo = (const float*)d_in[4];
    const float* bo = (const float*)d_in[5];
    const int*   pq = (const int*)d_in[6];
    const int*   pk = (const int*)d_in[7];
    float* out = (float*)d_out;

    float *xq, *xk, *q, *k, *v, *o, *wt;
    cudaGetSymbolAddress((void**)&xq, g_xq);
    cudaGetSymbolAddress((void**)&xk, g_xk);
    cudaGetSymbolAddress((void**)&q,  g_q);
    cudaGetSymbolAddress((void**)&k,  g_k);
    cudaGetSymbolAddress((void**)&v,  g_v);
    cudaGetSymbolAddress((void**)&o,  g_o);
    cudaGetSymbolAddress((void**)&wt, g_WT);

    const int ATTN_SMEM = 3 * 64 * ASTR2 * (int)sizeof(uint32_t);  // 52224 B
    cudaFuncSetAttribute(attn_mma_kernel,
                         cudaFuncAttributeMaxDynamicSharedMemorySize, ATTN_SMEM);

    // 0. weight transposes (W[k][n] -> WT[n][k])
    transpose_kernel<<<dim3(24, 24, 4), dim3(32, 8)>>>(Wq, Wk, Wv, Wo);

    // 1. gathers
    gather_kernel<<<dim3(LD / 1024, NB), 256>>>(x, pq, pk);

    // 2. q/k/v projections (tf32 mma.sync); V written transposed (b,h,dh,l)
    dim3 gg(ND / 128, NM / 128);   // (6, 128)
    gemm_mma<0><<<gg, 128>>>(xq, wt + 0*(size_t)ND*ND, q, nullptr);
    gemm_mma<0><<<gg, 128>>>(xk, wt + 1*(size_t)ND*ND, k, nullptr);
    gemm_mma<2><<<gg, 128>>>(x,  wt + 2*(size_t)ND*ND, v, nullptr);

    // 3. attention (tensor-core flash)
    attn_mma_kernel<<<dim3(NL / 64, NB * NH), 128, ATTN_SMEM>>>();

    // 4. output projection + bias (tf32 mma.sync)
    gemm_mma<1><<<gg, 128>>>(o, wt + 3*(size_t)ND*ND, out, bo);
}

// round 5
// speedup vs baseline: 3.0634x; 1.1467x over previous
#include <cuda_runtime.h>
#include <cstdint>

#define NB 16
#define NL 1024
#define ND 768
#define NH 12
#define NDH 64
#define LD (NL*ND)          // 786432
#define NM (NB*NL)          // 16384

// ---------------- scratch (static device globals; no allocation) ----------
__device__ float g_xq[NB*LD];            // gathered q input  (b, l*d)
__device__ float g_xk[NB*LD];            // gathered k input
__device__ float g_q [NM*ND];            // (b,h,l,dh)
__device__ float g_k [NM*ND];            // (b,h,l,dh)
__device__ float g_v [NM*ND];            // V^T: (b,h,dh,l)
__device__ float g_o [NM*ND];            // attention output (b,l,inner)
__device__ float g_WT[4*ND*ND];          // transposed weights [n][k]

// ---------------- helpers ---------------------------------------------------
__device__ __forceinline__ uint32_t f2tf32(float f) {
    uint32_t r;
    asm("cvt.rna.tf32.f32 %0, %1;" : "=r"(r) : "f"(f));
    return r;
}

__device__ __forceinline__ void mma_tf32(float c[4], const uint32_t a[4],
                                         const uint32_t b[2]) {
    asm volatile(
        "mma.sync.aligned.m16n8k8.row.col.f32.tf32.tf32.f32 "
        "{%0,%1,%2,%3}, {%4,%5,%6,%7}, {%8,%9}, {%0,%1,%2,%3};"
        : "+f"(c[0]), "+f"(c[1]), "+f"(c[2]), "+f"(c[3])
        : "r"(a[0]), "r"(a[1]), "r"(a[2]), "r"(a[3]), "r"(b[0]), "r"(b[1]));
}

// ---------------- weight transpose: g_WT[z][n][k] = W_z[k][n] ---------------
__global__ void __launch_bounds__(256) transpose_kernel(
    const float* __restrict__ Wq, const float* __restrict__ Wk,
    const float* __restrict__ Wv, const float* __restrict__ Wo)
{
    __shared__ float t[32][33];
    const float* src = (blockIdx.z == 0) ? Wq : (blockIdx.z == 1) ? Wk
                     : (blockIdx.z == 2) ? Wv : Wo;
    float* dst = g_WT + (size_t)blockIdx.z * ND * ND;
    int x0 = blockIdx.x * 32, y0 = blockIdx.y * 32;
    int tx = threadIdx.x, ty = threadIdx.y;          // 32 x 8
    #pragma unroll
    for (int j = 0; j < 32; j += 8)
        t[ty + j][tx] = src[(size_t)(y0 + ty + j) * ND + x0 + tx];
    __syncthreads();
    #pragma unroll
    for (int j = 0; j < 32; j += 8)
        dst[(size_t)(x0 + ty + j) * ND + y0 + tx] = t[tx][ty + j];
}

// ---------------- gather: xq[b][i] = x[b][permq[i]] -------------------------
__global__ void __launch_bounds__(256) gather_kernel(
    const float* __restrict__ x,
    const int*   __restrict__ pq,
    const int*   __restrict__ pk)
{
    int b  = blockIdx.y;
    int i4 = (blockIdx.x * 256 + threadIdx.x) * 4;
    const float* xb = x + (size_t)b * LD;

    int q0 = pq[i4+0], q1 = pq[i4+1], q2 = pq[i4+2], q3 = pq[i4+3];
    int k0 = pk[i4+0], k1 = pk[i4+1], k2 = pk[i4+2], k3 = pk[i4+3];

    float4 vq = make_float4(xb[q0], xb[q1], xb[q2], xb[q3]);
    float4 vk = make_float4(xb[k0], xb[k1], xb[k2], xb[k3]);

    *(float4*)&g_xq[(size_t)b*LD + i4] = vq;
    *(float4*)&g_xk[(size_t)b*LD + i4] = vk;
}

// ---------------- tf32 tensor-core GEMM (pipelined, 256 thr) -----------------
// C[16384,768] = A[16384,768] @ W[768,768]; BT = W^T in [n][k] layout.
// 8 warps (4m x 2n), warp tile 32x64. BK=32, 2-stage double buffer.
// mode 0: scatter C to (b,h,l,dh).  mode 1: row-major + bias.
// mode 2: scatter C to V^T layout (b,h,dh,l).
#define AS_STRIDE 36
#define TILE_WORDS (128*AS_STRIDE)
#define GEMM_SMEM (4*TILE_WORDS*4)      // 73728 B

__device__ __forceinline__ void gemm_core(
    const float* __restrict__ A,
    const float* __restrict__ BT,
    float*       __restrict__ C,
    const float* __restrict__ bias,
    int mode)
{
    extern __shared__ uint32_t smg[];
    uint32_t* Asm = smg;                      // [2][128][36]
    uint32_t* Bsm = smg + 2*TILE_WORDS;       // [2][128][36]

    int tid  = threadIdx.x;
    int lane = tid & 31, wid = tid >> 5;
    int wm = wid >> 1, wn = wid & 1;          // 4 x 2 warps
    int g = lane >> 2, t = lane & 3;
    int m0 = blockIdx.y * 128, n0 = blockIdx.x * 128;
    int lr = tid >> 3;          // 0..31
    int lc = tid & 7;           // 0..7

    float c[2][8][4];
    #pragma unroll
    for (int mt = 0; mt < 2; mt++)
        #pragma unroll
        for (int nt = 0; nt < 8; nt++)
            #pragma unroll
            for (int i = 0; i < 4; i++) c[mt][nt][i] = 0.f;

    // prologue: stage 0 <- k-tile 0
    #pragma unroll
    for (int it = 0; it < 4; it++) {
        int r = it * 32 + lr;
        float4 va = *(const float4*)&A [(size_t)(m0 + r) * ND + lc * 4];
        float4 vb = *(const float4*)&BT[(size_t)(n0 + r) * ND + lc * 4];
        *(uint4*)&Asm[r*AS_STRIDE + lc*4] = make_uint4(
            f2tf32(va.x), f2tf32(va.y), f2tf32(va.z), f2tf32(va.w));
        *(uint4*)&Bsm[r*AS_STRIDE + lc*4] = make_uint4(
            f2tf32(vb.x), f2tf32(vb.y), f2tf32(vb.z), f2tf32(vb.w));
    }
    __syncthreads();

    for (int kt = 0; kt < 24; kt++) {
        int st = kt & 1;
        float4 na[4], nb[4];
        if (kt < 23) {
            #pragma unroll
            for (int it = 0; it < 4; it++) {
                int r = it * 32 + lr;
                na[it] = *(const float4*)&A [(size_t)(m0 + r) * ND + (kt+1)*32 + lc*4];
                nb[it] = *(const float4*)&BT[(size_t)(n0 + r) * ND + (kt+1)*32 + lc*4];
            }
        }

        const uint32_t* As = Asm + st * TILE_WORDS;
        const uint32_t* Bs = Bsm + st * TILE_WORDS;
        #pragma unroll
        for (int kk = 0; kk < 4; kk++) {
            int k0 = kk * 8 + t;
            uint32_t a[2][4], b[8][2];
            #pragma unroll
            for (int mt = 0; mt < 2; mt++) {
                int mr = wm * 32 + mt * 16 + g;
                a[mt][0] = As[mr * AS_STRIDE + k0];
                a[mt][1] = As[(mr + 8) * AS_STRIDE + k0];
                a[mt][2] = As[mr * AS_STRIDE + k0 + 4];
                a[mt][3] = As[(mr + 8) * AS_STRIDE + k0 + 4];
            }
            #pragma unroll
            for (int nt = 0; nt < 8; nt++) {
                int nr = wn * 64 + nt * 8 + g;
                b[nt][0] = Bs[nr * AS_STRIDE + k0];
                b[nt][1] = Bs[nr * AS_STRIDE + k0 + 4];
            }
            #pragma unroll
            for (int mt = 0; mt < 2; mt++)
                #pragma unroll
                for (int nt = 0; nt < 8; nt++)
                    mma_tf32(c[mt][nt], a[mt], b[nt]);
        }

        if (kt < 23) {
            uint32_t* da = Asm + (st ^ 1) * TILE_WORDS;
            uint32_t* db = Bsm + (st ^ 1) * TILE_WORDS;
            #pragma unroll
            for (int it = 0; it < 4; it++) {
                int r = it * 32 + lr;
                *(uint4*)&da[r*AS_STRIDE + lc*4] = make_uint4(
                    f2tf32(na[it].x), f2tf32(na[it].y),
                    f2tf32(na[it].z), f2tf32(na[it].w));
                *(uint4*)&db[r*AS_STRIDE + lc*4] = make_uint4(
                    f2tf32(nb[it].x), f2tf32(nb[it].y),
                    f2tf32(nb[it].z), f2tf32(nb[it].w));
            }
        }
        __syncthreads();
    }

    // epilogue
    #pragma unroll
    for (int mt = 0; mt < 2; mt++) {
        int m = m0 + wm * 32 + mt * 16 + g;
        #pragma unroll
        for (int nt = 0; nt < 8; nt++) {
            int n = n0 + wn * 64 + nt * 8 + 2 * t;
            if (mode == 0) {
                int b0i = m >> 10, l = m & 1023;
                int h = n >> 6, dh = n & 63;
                size_t base0 = ((((size_t)b0i * NH + h) * NL + l) << 6) + dh;
                *(float2*)&C[base0] = make_float2(c[mt][nt][0], c[mt][nt][1]);
                size_t base2 = ((((size_t)b0i * NH + h) * NL + (l + 8)) << 6) + dh;
                *(float2*)&C[base2] = make_float2(c[mt][nt][2], c[mt][nt][3]);
            } else if (mode == 2) {
                int b0i = m >> 10, l = m & 1023;
                int h = n >> 6, dh = n & 63;
                size_t base = (((size_t)b0i * NH + h) * NDH + dh) * NL + l;
                C[base]          = c[mt][nt][0];
                C[base + NL]     = c[mt][nt][1];
                C[base + 8]      = c[mt][nt][2];
                C[base + NL + 8] = c[mt][nt][3];
            } else {
                float2 bb = *(const float2*)&bias[n];
                *(float2*)&C[(size_t)m * ND + n] =
                    make_float2(c[mt][nt][0] + bb.x, c[mt][nt][1] + bb.y);
                *(float2*)&C[(size_t)(m + 8) * ND + n] =
                    make_float2(c[mt][nt][2] + bb.x, c[mt][nt][3] + bb.y);
            }
        }
    }
}

// fused q/k/v projections: blockIdx.z selects which GEMM
__global__ void __launch_bounds__(256) qkv_kernel(const float* __restrict__ x)
{
    int z = blockIdx.z;
    const float* A  = (z == 0) ? g_xq : (z == 1) ? g_xk : x;
    const float* BT = g_WT + (size_t)z * ND * ND;
    float* C        = (z == 0) ? g_q : (z == 1) ? g_k : g_v;
    gemm_core(A, BT, C, nullptr, (z == 2) ? 2 : 0);
}

// final projection + bias
__global__ void __launch_bounds__(256) proj_kernel(
    const float* __restrict__ bias, float* __restrict__ out)
{
    gemm_core(g_o, g_WT + 3 * (size_t)ND * ND, out, bias, 1);
}

// ---------------- tensor-core flash attention (tf32 mma) --------------------
// grid (16 q-tiles, 192 bh), block 128 (4 warps x 16 rows).
#define ASTR2 68

__global__ void __launch_bounds__(128) attn_mma_kernel()
{
    extern __shared__ uint32_t smu[];
    uint32_t (*Ks)[ASTR2] = (uint32_t(*)[ASTR2])smu;
    uint32_t (*Vs)[ASTR2] = (uint32_t(*)[ASTR2])(smu + 64*ASTR2);
    uint32_t (*Ps)[ASTR2] = (uint32_t(*)[ASTR2])(smu + 2*64*ASTR2);

    int tid = threadIdx.x, lane = tid & 31, wid = tid >> 5;
    int g = lane >> 2, t = lane & 3;
    int bh = blockIdx.y, qt = blockIdx.x;
    int mrow = wid * 16 + g;

    const float* Qg  = g_q + (size_t)bh * NL * NDH + (size_t)qt * 64 * NDH;
    const float* Kg  = g_k + (size_t)bh * NL * NDH;
    const float* VTg = g_v + (size_t)bh * NDH * NL;

    #pragma unroll
    for (int it = 0; it < 8; it++) {
        int idx = it * 128 + tid;
        int r = idx >> 4, c4 = (idx & 15) << 2;
        float4 v = *(const float4*)&Qg[r * 64 + c4];
        Ks[r][c4+0] = f2tf32(v.x); Ks[r][c4+1] = f2tf32(v.y);
        Ks[r][c4+2] = f2tf32(v.z); Ks[r][c4+3] = f2tf32(v.w);
    }
    __syncthreads();
    uint32_t aq[8][4];
    #pragma unroll
    for (int kk = 0; kk < 8; kk++) {
        aq[kk][0] = Ks[mrow][kk*8 + t];
        aq[kk][1] = Ks[mrow + 8][kk*8 + t];
        aq[kk][2] = Ks[mrow][kk*8 + t + 4];
        aq[kk][3] = Ks[mrow + 8][kk*8 + t + 4];
    }

    float mI0 = -1e30f, mI1 = -1e30f, lI0 = 0.f, lI1 = 0.f;
    float o[8][4];
    #pragma unroll
    for (int nt = 0; nt < 8; nt++)
        #pragma unroll
        for (int i = 0; i < 4; i++) o[nt][i] = 0.f;

    for (int kt = 0; kt < 16; kt++) {
        __syncthreads();
        const float* Kt = Kg + (size_t)kt * 64 * 64;
        #pragma unroll
        for (int it = 0; it < 8; it++) {
            int idx = it * 128 + tid;
            int r = idx >> 4, c4 = (idx & 15) << 2;
            float4 v = *(const float4*)&Kt[r * 64 + c4];
            Ks[r][c4+0] = f2tf32(v.x); Ks[r][c4+1] = f2tf32(v.y);
            Ks[r][c4+2] = f2tf32(v.z); Ks[r][c4+3] = f2tf32(v.w);
            float4 u = *(const float4*)&VTg[(size_t)r * NL + kt * 64 + c4];
            Vs[r][c4+0] = f2tf32(u.x); Vs[r][c4+1] = f2tf32(u.y);
            Vs[r][c4+2] = f2tf32(u.z); Vs[r][c4+3] = f2tf32(u.w);
        }
        __syncthreads();

        float s[8][4];
        #pragma unroll
        for (int nt = 0; nt < 8; nt++)
            #pragma unroll
            for (int i = 0; i < 4; i++) s[nt][i] = 0.f;
        #pragma unroll
        for (int kk = 0; kk < 8; kk++) {
            #pragma unroll
            for (int nt = 0; nt < 8; nt++) {
                uint32_t b[2];
                int nr = nt * 8 + g;
                b[0] = Ks[nr][kk*8 + t];
                b[1] = Ks[nr][kk*8 + t + 4];
                mma_tf32(s[nt], aq[kk], b);
            }
        }
        #pragma unroll
        for (int nt = 0; nt < 8; nt++)
            #pragma unroll
            for (int i = 0; i < 4; i++) s[nt][i] *= 0.125f;

        float mx0 = -1e30f, mx1 = -1e30f;
        #pragma unroll
        for (int nt = 0; nt < 8; nt++) {
            mx0 = fmaxf(mx0, fmaxf(s[nt][0], s[nt][1]));
            mx1 = fmaxf(mx1, fmaxf(s[nt][2], s[nt][3]));
        }
        mx0 = fmaxf(mx0, __shfl_xor_sync(0xffffffffu, mx0, 1));
        mx0 = fmaxf(mx0, __shfl_xor_sync(0xffffffffu, mx0, 2));
        mx1 = fmaxf(mx1, __shfl_xor_sync(0xffffffffu, mx1, 1));
        mx1 = fmaxf(mx1, __shfl_xor_sync(0xffffffffu, mx1, 2));

        float mn0 = fmaxf(mI0, mx0), mn1 = fmaxf(mI1, mx1);
        float corr0 = __expf(mI0 - mn0), corr1 = __expf(mI1 - mn1);
        mI0 = mn0; mI1 = mn1;

        float sum0 = 0.f, sum1 = 0.f;
        #pragma unroll
        for (int nt = 0; nt < 8; nt++) {
            float p0 = __expf(s[nt][0] - mn0);
            float p1 = __expf(s[nt][1] - mn0);
            float p2 = __expf(s[nt][2] - mn1);
            float p3 = __expf(s[nt][3] - mn1);
            sum0 += p0 + p1; sum1 += p2 + p3;
            int col = nt * 8 + 2 * t;
            *(uint2*)&Ps[mrow][col]     = make_uint2(f2tf32(p0), f2tf32(p1));
            *(uint2*)&Ps[mrow + 8][col] = make_uint2(f2tf32(p2), f2tf32(p3));
        }
        sum0 += __shfl_xor_sync(0xffffffffu, sum0, 1);
        sum0 += __shfl_xor_sync(0xffffffffu, sum0, 2);
        sum1 += __shfl_xor_sync(0xffffffffu, sum1, 1);
        sum1 += __shfl_xor_sync(0xffffffffu, sum1, 2);
        lI0 = lI0 * corr0 + sum0;
        lI1 = lI1 * corr1 + sum1;

        #pragma unroll
        for (int nt = 0; nt < 8; nt++) {
            o[nt][0] *= corr0; o[nt][1] *= corr0;
            o[nt][2] *= corr1; o[nt][3] *= corr1;
        }
        __syncwarp();

        #pragma unroll
        for (int kk = 0; kk < 8; kk++) {
            uint32_t ap[4];
            ap[0] = Ps[mrow][kk*8 + t];
            ap[1] = Ps[mrow + 8][kk*8 + t];
            ap[2] = Ps[mrow][kk*8 + t + 4];
            ap[3] = Ps[mrow + 8][kk*8 + t + 4];
            #pragma unroll
            for (int nt = 0; nt < 8; nt++) {
                uint32_t b[2];
                int nr = nt * 8 + g;
                b[0] = Vs[nr][kk*8 + t];
                b[1] = Vs[nr][kk*8 + t + 4];
                mma_tf32(o[nt], ap, b);
            }
        }
    }

    float inv0 = 1.f / lI0, inv1 = 1.f / lI1;
    int b = bh / NH, h = bh % NH;
    float* Og = g_o + ((size_t)b * NL + qt * 64) * ND + h * 64;
    #pragma unroll
    for (int nt = 0; nt < 8; nt++) {
        int col = nt * 8 + 2 * t;
        *(float2*)&Og[(size_t)mrow * ND + col] =
            make_float2(o[nt][0] * inv0, o[nt][1] * inv0);
        *(float2*)&Og[(size_t)(mrow + 8) * ND + col] =
            make_float2(o[nt][2] * inv1, o[nt][3] * inv1);
    }
}

// ---------------- launch -----------------------------------------------------
extern "C" void kernel_launch(void* const* d_in, const int* in_sizes, int n_in,
                              void* d_out, int out_size)
{
    const float* x  = (const float*)d_in[0];
    const float* Wq = (const float*)d_in[1];
    const float* Wk = (const float*)d_in[2];
    const float* Wv = (const float*)d_in[3];
    const float* Wo = (const float*)d_in[4];
    const float* bo = (const float*)d_in[5];
    const int*   pq = (const int*)d_in[6];
    const int*   pk = (const int*)d_in[7];
    float* out = (float*)d_out;

    const int ATTN_SMEM = 3 * 64 * ASTR2 * (int)sizeof(uint32_t);  // 52224 B
    cudaFuncSetAttribute(attn_mma_kernel,
                         cudaFuncAttributeMaxDynamicSharedMemorySize, ATTN_SMEM);
    cudaFuncSetAttribute(qkv_kernel,
                         cudaFuncAttributeMaxDynamicSharedMemorySize, GEMM_SMEM);
    cudaFuncSetAttribute(proj_kernel,
                         cudaFuncAttributeMaxDynamicSharedMemorySize, GEMM_SMEM);

    // 0. weight transposes (W[k][n] -> WT[n][k])
    transpose_kernel<<<dim3(24, 24, 4), dim3(32, 8)>>>(Wq, Wk, Wv, Wo);

    // 1. gathers
    gather_kernel<<<dim3(LD / 1024, NB), 256>>>(x, pq, pk);

    // 2. fused q/k/v projections (pipelined tf32 mma)
    qkv_kernel<<<dim3(ND / 128, NM / 128, 3), 256, GEMM_SMEM>>>(x);

    // 3. attention (tensor-core flash)
    attn_mma_kernel<<<dim3(NL / 64, NB * NH), 128, ATTN_SMEM>>>();

    // 4. output projection + bias
    proj_kernel<<<dim3(ND / 128, NM / 128), 256, GEMM_SMEM>>>(bo, out);
}

// round 6
// speedup vs baseline: 3.1817x; 1.0386x over previous
#include <cuda_runtime.h>
#include <cstdint>

#define NB 16
#define NL 1024
#define ND 768
#define NH 12
#define NDH 64
#define LD (NL*ND)          // 786432
#define NM (NB*NL)          // 16384

// ---------------- scratch (static device globals; no allocation) ----------
__device__ float g_xq[NB*LD];            // gathered q input  (b, l*d)
__device__ float g_xk[NB*LD];            // gathered k input
__device__ float g_q [NM*ND];            // (b,h,l,dh), tf32 bits, pre-scaled
__device__ float g_k [NM*ND];            // (b,h,l,dh), tf32 bits
__device__ float g_v [NM*ND];            // V^T: (b,h,dh,l), tf32 bits
__device__ float g_o [NM*ND];            // attention output (b,l,inner), fp32
__device__ float g_WT[4*ND*ND];          // transposed weights [n][k]

// 0.125 * log2(e)
#define SC_Q 0.18033688011112042f

// ---------------- helpers ---------------------------------------------------
__device__ __forceinline__ uint32_t f2tf32(float f) {
    uint32_t r;
    asm("cvt.rna.tf32.f32 %0, %1;" : "=r"(r) : "f"(f));
    return r;
}
__device__ __forceinline__ float tf32f(float f) {
    return __uint_as_float(f2tf32(f));
}
__device__ __forceinline__ float ex2(float x) {
    float r;
    asm("ex2.approx.f32 %0, %1;" : "=f"(r) : "f"(x));
    return r;
}

__device__ __forceinline__ void mma_tf32(float c[4], const uint32_t a[4],
                                         const uint32_t b[2]) {
    asm volatile(
        "mma.sync.aligned.m16n8k8.row.col.f32.tf32.tf32.f32 "
        "{%0,%1,%2,%3}, {%4,%5,%6,%7}, {%8,%9}, {%0,%1,%2,%3};"
        : "+f"(c[0]), "+f"(c[1]), "+f"(c[2]), "+f"(c[3])
        : "r"(a[0]), "r"(a[1]), "r"(a[2]), "r"(a[3]), "r"(b[0]), "r"(b[1]));
}

// ---------------- weight transpose: g_WT[z][n][k] = W_z[k][n] ---------------
__global__ void __launch_bounds__(256) transpose_kernel(
    const float* __restrict__ Wq, const float* __restrict__ Wk,
    const float* __restrict__ Wv, const float* __restrict__ Wo)
{
    __shared__ float t[32][33];
    const float* src = (blockIdx.z == 0) ? Wq : (blockIdx.z == 1) ? Wk
                     : (blockIdx.z == 2) ? Wv : Wo;
    float* dst = g_WT + (size_t)blockIdx.z * ND * ND;
    int x0 = blockIdx.x * 32, y0 = blockIdx.y * 32;
    int tx = threadIdx.x, ty = threadIdx.y;          // 32 x 8
    #pragma unroll
    for (int j = 0; j < 32; j += 8)
        t[ty + j][tx] = src[(size_t)(y0 + ty + j) * ND + x0 + tx];
    __syncthreads();
    #pragma unroll
    for (int j = 0; j < 32; j += 8)
        dst[(size_t)(x0 + ty + j) * ND + y0 + tx] = t[tx][ty + j];
}

// ---------------- gather: xq[b][i] = x[b][permq[i]] -------------------------
__global__ void __launch_bounds__(256) gather_kernel(
    const float* __restrict__ x,
    const int*   __restrict__ pq,
    const int*   __restrict__ pk)
{
    int b  = blockIdx.y;
    int i4 = (blockIdx.x * 256 + threadIdx.x) * 4;
    const float* xb = x + (size_t)b * LD;

    int q0 = pq[i4+0], q1 = pq[i4+1], q2 = pq[i4+2], q3 = pq[i4+3];
    int k0 = pk[i4+0], k1 = pk[i4+1], k2 = pk[i4+2], k3 = pk[i4+3];

    float4 vq = make_float4(xb[q0], xb[q1], xb[q2], xb[q3]);
    float4 vk = make_float4(xb[k0], xb[k1], xb[k2], xb[k3]);

    *(float4*)&g_xq[(size_t)b*LD + i4] = vq;
    *(float4*)&g_xk[(size_t)b*LD + i4] = vk;
}

// ---------------- tf32 tensor-core GEMM (pipelined, 256 thr) -----------------
// mode 0: scatter C to (b,h,l,dh), values tf32(c*osc).
// mode 1: row-major + bias (fp32).
// mode 2: scatter C to V^T (b,h,dh,l), values tf32(c).
#define AS_STRIDE 36
#define TILE_WORDS (128*AS_STRIDE)
#define GEMM_SMEM (4*TILE_WORDS*4)      // 73728 B

__device__ __forceinline__ void gemm_core(
    const float* __restrict__ A,
    const float* __restrict__ BT,
    float*       __restrict__ C,
    const float* __restrict__ bias,
    int mode, float osc)
{
    extern __shared__ uint32_t smg[];
    uint32_t* Asm = smg;                      // [2][128][36]
    uint32_t* Bsm = smg + 2*TILE_WORDS;       // [2][128][36]

    int tid  = threadIdx.x;
    int lane = tid & 31, wid = tid >> 5;
    int wm = wid >> 1, wn = wid & 1;          // 4 x 2 warps
    int g = lane >> 2, t = lane & 3;
    int m0 = blockIdx.y * 128, n0 = blockIdx.x * 128;
    int lr = tid >> 3;          // 0..31
    int lc = tid & 7;           // 0..7

    float c[2][8][4];
    #pragma unroll
    for (int mt = 0; mt < 2; mt++)
        #pragma unroll
        for (int nt = 0; nt < 8; nt++)
            #pragma unroll
            for (int i = 0; i < 4; i++) c[mt][nt][i] = 0.f;

    #pragma unroll
    for (int it = 0; it < 4; it++) {
        int r = it * 32 + lr;
        float4 va = *(const float4*)&A [(size_t)(m0 + r) * ND + lc * 4];
        float4 vb = *(const float4*)&BT[(size_t)(n0 + r) * ND + lc * 4];
        *(uint4*)&Asm[r*AS_STRIDE + lc*4] = make_uint4(
            f2tf32(va.x), f2tf32(va.y), f2tf32(va.z), f2tf32(va.w));
        *(uint4*)&Bsm[r*AS_STRIDE + lc*4] = make_uint4(
            f2tf32(vb.x), f2tf32(vb.y), f2tf32(vb.z), f2tf32(vb.w));
    }
    __syncthreads();

    for (int kt = 0; kt < 24; kt++) {
        int st = kt & 1;
        float4 na[4], nb[4];
        if (kt < 23) {
            #pragma unroll
            for (int it = 0; it < 4; it++) {
                int r = it * 32 + lr;
                na[it] = *(const float4*)&A [(size_t)(m0 + r) * ND + (kt+1)*32 + lc*4];
                nb[it] = *(const float4*)&BT[(size_t)(n0 + r) * ND + (kt+1)*32 + lc*4];
            }
        }

        const uint32_t* As = Asm + st * TILE_WORDS;
        const uint32_t* Bs = Bsm + st * TILE_WORDS;
        #pragma unroll
        for (int kk = 0; kk < 4; kk++) {
            int k0 = kk * 8 + t;
            uint32_t a[2][4], b[8][2];
            #pragma unroll
            for (int mt = 0; mt < 2; mt++) {
                int mr = wm * 32 + mt * 16 + g;
                a[mt][0] = As[mr * AS_STRIDE + k0];
                a[mt][1] = As[(mr + 8) * AS_STRIDE + k0];
                a[mt][2] = As[mr * AS_STRIDE + k0 + 4];
                a[mt][3] = As[(mr + 8) * AS_STRIDE + k0 + 4];
            }
            #pragma unroll
            for (int nt = 0; nt < 8; nt++) {
                int nr = wn * 64 + nt * 8 + g;
                b[nt][0] = Bs[nr * AS_STRIDE + k0];
                b[nt][1] = Bs[nr * AS_STRIDE + k0 + 4];
            }
            #pragma unroll
            for (int mt = 0; mt < 2; mt++)
                #pragma unroll
                for (int nt = 0; nt < 8; nt++)
                    mma_tf32(c[mt][nt], a[mt], b[nt]);
        }

        if (kt < 23) {
            uint32_t* da = Asm + (st ^ 1) * TILE_WORDS;
            uint32_t* db = Bsm + (st ^ 1) * TILE_WORDS;
            #pragma unroll
            for (int it = 0; it < 4; it++) {
                int r = it * 32 + lr;
                *(uint4*)&da[r*AS_STRIDE + lc*4] = make_uint4(
                    f2tf32(na[it].x), f2tf32(na[it].y),
                    f2tf32(na[it].z), f2tf32(na[it].w));
                *(uint4*)&db[r*AS_STRIDE + lc*4] = make_uint4(
                    f2tf32(nb[it].x), f2tf32(nb[it].y),
                    f2tf32(nb[it].z), f2tf32(nb[it].w));
            }
        }
        __syncthreads();
    }

    // epilogue
    #pragma unroll
    for (int mt = 0; mt < 2; mt++) {
        int m = m0 + wm * 32 + mt * 16 + g;
        #pragma unroll
        for (int nt = 0; nt < 8; nt++) {
            int n = n0 + wn * 64 + nt * 8 + 2 * t;
            if (mode == 0) {
                int b0i = m >> 10, l = m & 1023;
                int h = n >> 6, dh = n & 63;
                size_t base0 = ((((size_t)b0i * NH + h) * NL + l) << 6) + dh;
                *(float2*)&C[base0] = make_float2(
                    tf32f(c[mt][nt][0]*osc), tf32f(c[mt][nt][1]*osc));
                size_t base2 = ((((size_t)b0i * NH + h) * NL + (l + 8)) << 6) + dh;
                *(float2*)&C[base2] = make_float2(
                    tf32f(c[mt][nt][2]*osc), tf32f(c[mt][nt][3]*osc));
            } else if (mode == 2) {
                int b0i = m >> 10, l = m & 1023;
                int h = n >> 6, dh = n & 63;
                size_t base = (((size_t)b0i * NH + h) * NDH + dh) * NL + l;
                C[base]          = tf32f(c[mt][nt][0]);
                C[base + NL]     = tf32f(c[mt][nt][1]);
                C[base + 8]      = tf32f(c[mt][nt][2]);
                C[base + NL + 8] = tf32f(c[mt][nt][3]);
            } else {
                float2 bb = *(const float2*)&bias[n];
                *(float2*)&C[(size_t)m * ND + n] =
                    make_float2(c[mt][nt][0] + bb.x, c[mt][nt][1] + bb.y);
                *(float2*)&C[(size_t)(m + 8) * ND + n] =
                    make_float2(c[mt][nt][2] + bb.x, c[mt][nt][3] + bb.y);
            }
        }
    }
}

// fused q/k/v projections: blockIdx.z selects which GEMM
__global__ void __launch_bounds__(256) qkv_kernel(const float* __restrict__ x)
{
    int z = blockIdx.z;
    const float* A  = (z == 0) ? g_xq : (z == 1) ? g_xk : x;
    const float* BT = g_WT + (size_t)z * ND * ND;
    float* C        = (z == 0) ? g_q : (z == 1) ? g_k : g_v;
    float osc       = (z == 0) ? SC_Q : 1.0f;
    gemm_core(A, BT, C, nullptr, (z == 2) ? 2 : 0, osc);
}

// final projection + bias
__global__ void __launch_bounds__(256) proj_kernel(
    const float* __restrict__ bias, float* __restrict__ out)
{
    gemm_core(g_o, g_WT + 3 * (size_t)ND * ND, out, bias, 1, 1.0f);
}

// ---------------- tensor-core flash attention (tf32 mma) --------------------
// grid (8 q-tiles of 128, 192 bh), block 128 (4 warps, warp = 32 q-rows).
// All of g_q/g_k/g_v hold tf32 bit patterns; Q pre-scaled by 0.125*log2e.
#define ASTR2 68

__global__ void __launch_bounds__(128) attn_mma_kernel()
{
    extern __shared__ uint32_t smu[];
    uint32_t (*Ks)[ASTR2] = (uint32_t(*)[ASTR2])smu;               // 64 rows
    uint32_t (*Vs)[ASTR2] = (uint32_t(*)[ASTR2])(smu + 64*ASTR2);  // 64 rows
    uint32_t (*Ps)[ASTR2] = (uint32_t(*)[ASTR2])(smu + 128*ASTR2); // 128 rows (Q staging too)

    int tid = threadIdx.x, lane = tid & 31, wid = tid >> 5;
    int g = lane >> 2, t = lane & 3;
    int bh = blockIdx.y, qt = blockIdx.x;

    const float* Qg  = g_q + (size_t)bh * NL * NDH + (size_t)qt * 128 * NDH;
    const float* Kg  = g_k + (size_t)bh * NL * NDH;
    const float* VTg = g_v + (size_t)bh * NDH * NL;

    // stage Q (128 x 64, already tf32 bits)
    #pragma unroll
    for (int it = 0; it < 16; it++) {
        int idx = it * 128 + tid;
        int r = idx >> 4, c4 = (idx & 15) << 2;
        *(uint4*)&Ps[r][c4] = *(const uint4*)&Qg[r * 64 + c4];
    }
    __syncthreads();

    uint32_t aq[2][8][4];
    #pragma unroll
    for (int h = 0; h < 2; h++) {
        int mr = wid * 32 + h * 16 + g;
        #pragma unroll
        for (int kk = 0; kk < 8; kk++) {
            aq[h][kk][0] = Ps[mr][kk*8 + t];
            aq[h][kk][1] = Ps[mr + 8][kk*8 + t];
            aq[h][kk][2] = Ps[mr][kk*8 + t + 4];
            aq[h][kk][3] = Ps[mr + 8][kk*8 + t + 4];
        }
    }

    float mI[2][2], lI[2][2];
    #pragma unroll
    for (int h = 0; h < 2; h++) { mI[h][0] = mI[h][1] = -1e30f; lI[h][0] = lI[h][1] = 0.f; }
    float o[2][8][4];
    #pragma unroll
    for (int h = 0; h < 2; h++)
        #pragma unroll
        for (int nt = 0; nt < 8; nt++)
            #pragma unroll
            for (int i = 0; i < 4; i++) o[h][nt][i] = 0.f;

    for (int kt = 0; kt < 16; kt++) {
        __syncthreads();   // prev-iter Ks/Vs readers done
        const float* Kt = Kg + (size_t)kt * 64 * 64;
        #pragma unroll
        for (int it = 0; it < 8; it++) {
            int idx = it * 128 + tid;
            int r = idx >> 4, c4 = (idx & 15) << 2;
            *(uint4*)&Ks[r][c4] = *(const uint4*)&Kt[r * 64 + c4];
            *(uint4*)&Vs[r][c4] = *(const uint4*)&VTg[(size_t)r * NL + kt * 64 + c4];
        }
        __syncthreads();

        #pragma unroll
        for (int h = 0; h < 2; h++) {
            int mr = wid * 32 + h * 16 + g;
            float s[8][4];
            #pragma unroll
            for (int nt = 0; nt < 8; nt++)
                #pragma unroll
                for (int i = 0; i < 4; i++) s[nt][i] = 0.f;
            #pragma unroll
            for (int kk = 0; kk < 8; kk++) {
                #pragma unroll
                for (int nt = 0; nt < 8; nt++) {
                    uint32_t b[2];
                    int nr = nt * 8 + g;
                    b[0] = Ks[nr][kk*8 + t];
                    b[1] = Ks[nr][kk*8 + t + 4];
                    mma_tf32(s[nt], aq[h][kk], b);
                }
            }
            // online softmax in log2 domain (scale folded into Q)
            float mx0 = -1e30f, mx1 = -1e30f;
            #pragma unroll
            for (int nt = 0; nt < 8; nt++) {
                mx0 = fmaxf(mx0, fmaxf(s[nt][0], s[nt][1]));
                mx1 = fmaxf(mx1, fmaxf(s[nt][2], s[nt][3]));
            }
            mx0 = fmaxf(mx0, __shfl_xor_sync(0xffffffffu, mx0, 1));
            mx0 = fmaxf(mx0, __shfl_xor_sync(0xffffffffu, mx0, 2));
            mx1 = fmaxf(mx1, __shfl_xor_sync(0xffffffffu, mx1, 1));
            mx1 = fmaxf(mx1, __shfl_xor_sync(0xffffffffu, mx1, 2));

            float mn0 = fmaxf(mI[h][0], mx0), mn1 = fmaxf(mI[h][1], mx1);
            float corr0 = ex2(mI[h][0] - mn0), corr1 = ex2(mI[h][1] - mn1);
            mI[h][0] = mn0; mI[h][1] = mn1;

            float sum0 = 0.f, sum1 = 0.f;
            #pragma unroll
            for (int nt = 0; nt < 8; nt++) {
                float p0 = ex2(s[nt][0] - mn0);
                float p1 = ex2(s[nt][1] - mn0);
                float p2 = ex2(s[nt][2] - mn1);
                float p3 = ex2(s[nt][3] - mn1);
                sum0 += p0 + p1; sum1 += p2 + p3;
                int col = nt * 8 + 2 * t;
                *(uint2*)&Ps[mr][col]     = make_uint2(f2tf32(p0), f2tf32(p1));
                *(uint2*)&Ps[mr + 8][col] = make_uint2(f2tf32(p2), f2tf32(p3));
            }
            sum0 += __shfl_xor_sync(0xffffffffu, sum0, 1);
            sum0 += __shfl_xor_sync(0xffffffffu, sum0, 2);
            sum1 += __shfl_xor_sync(0xffffffffu, sum1, 1);
            sum1 += __shfl_xor_sync(0xffffffffu, sum1, 2);
            lI[h][0] = lI[h][0] * corr0 + sum0;
            lI[h][1] = lI[h][1] * corr1 + sum1;

            #pragma unroll
            for (int nt = 0; nt < 8; nt++) {
                o[h][nt][0] *= corr0; o[h][nt][1] *= corr0;
                o[h][nt][2] *= corr1; o[h][nt][3] *= corr1;
            }
        }
        __syncwarp();

        // O += P @ V : V b-fragments shared across both halves
        #pragma unroll
        for (int kk = 0; kk < 8; kk++) {
            uint32_t vb[8][2];
            #pragma unroll
            for (int nt = 0; nt < 8; nt++) {
                int nr = nt * 8 + g;
                vb[nt][0] = Vs[nr][kk*8 + t];
                vb[nt][1] = Vs[nr][kk*8 + t + 4];
            }
            #pragma unroll
            for (int h = 0; h < 2; h++) {
                int mr = wid * 32 + h * 16 + g;
                uint32_t ap[4];
                ap[0] = Ps[mr][kk*8 + t];
                ap[1] = Ps[mr + 8][kk*8 + t];
                ap[2] = Ps[mr][kk*8 + t + 4];
                ap[3] = Ps[mr + 8][kk*8 + t + 4];
                #pragma unroll
                for (int nt = 0; nt < 8; nt++)
                    mma_tf32(o[h][nt], ap, vb[nt]);
            }
        }
    }

    // epilogue
    int bb = bh / NH, hh = bh % NH;
    float* Og = g_o + ((size_t)bb * NL + qt * 128) * ND + hh * 64;
    #pragma unroll
    for (int h = 0; h < 2; h++) {
        float inv0 = 1.f / lI[h][0], inv1 = 1.f / lI[h][1];
        int mr = wid * 32 + h * 16 + g;
        #pragma unroll
        for (int nt = 0; nt < 8; nt++) {
            int col = nt * 8 + 2 * t;
            *(float2*)&Og[(size_t)mr * ND + col] =
                make_float2(o[h][nt][0] * inv0, o[h][nt][1] * inv0);
            *(float2*)&Og[(size_t)(mr + 8) * ND + col] =
                make_float2(o[h][nt][2] * inv1, o[h][nt][3] * inv1);
        }
    }
}

// ---------------- launch -----------------------------------------------------
extern "C" void kernel_launch(void* const* d_in, const int* in_sizes, int n_in,
                              void* d_out, int out_size)
{
    const float* x  = (const float*)d_in[0];
    const float* Wq = (const float*)d_in[1];
    const float* Wk = (const float*)d_in[2];
    const float* Wv = (const float*)d_in[3];
    const float* Wo = (const float*)d_in[4];
    const float* bo = (const float*)d_in[5];
    const int*   pq = (const int*)d_in[6];
    const int*   pk = (const int*)d_in[7];
    float* out = (float*)d_out;

    const int ATTN_SMEM = 256 * ASTR2 * (int)sizeof(uint32_t);  // 69632 B
    cudaFuncSetAttribute(attn_mma_kernel,
                         cudaFuncAttributeMaxDynamicSharedMemorySize, ATTN_SMEM);
    cudaFuncSetAttribute(qkv_kernel,
                         cudaFuncAttributeMaxDynamicSharedMemorySize, GEMM_SMEM);
    cudaFuncSetAttribute(proj_kernel,
                         cudaFuncAttributeMaxDynamicSharedMemorySize, GEMM_SMEM);

    // 0. weight transposes (W[k][n] -> WT[n][k])
    transpose_kernel<<<dim3(24, 24, 4), dim3(32, 8)>>>(Wq, Wk, Wv, Wo);

    // 1. gathers
    gather_kernel<<<dim3(LD / 1024, NB), 256>>>(x, pq, pk);

    // 2. fused q/k/v projections (pipelined tf32 mma)
    qkv_kernel<<<dim3(ND / 128, NM / 128, 3), 256, GEMM_SMEM>>>(x);

    // 3. attention (tensor-core flash, 128-row q blocks)
    attn_mma_kernel<<<dim3(NL / 128, NB * NH), 128, ATTN_SMEM>>>();

    // 4. output projection + bias
    proj_kernel<<<dim3(ND / 128, NM / 128), 256, GEMM_SMEM>>>(bo, out);
}

// round 8
// speedup vs baseline: 3.3268x; 1.0456x over previous
#include <cuda_runtime.h>
#include <cstdint>

#define NB 16
#define NL 1024
#define ND 768
#define NH 12
#define NDH 64
#define LD (NL*ND)          // 786432
#define NM (NB*NL)          // 16384

// ---------------- scratch (static device globals; no allocation) ----------
__device__ float g_xq[NB*LD];            // gathered q input, tf32 bits
__device__ float g_xk[NB*LD];            // gathered k input, tf32 bits
__device__ float g_xv[NB*LD];            // x copy, tf32 bits
__device__ float g_q [NM*ND];            // (b,h,l,dh), tf32 bits, pre-scaled
__device__ float g_k [NM*ND];            // (b,h,l,dh), tf32 bits
__device__ float g_v [NM*ND];            // V^T: (b,h,dh,l), tf32 bits
__device__ float g_o [NM*ND];            // attention output, tf32 bits
__device__ float g_WT[4*ND*ND];          // transposed weights [n][k], tf32 bits

// 0.125 * log2(e)
#define SC_Q 0.18033688011112042f

// ---------------- helpers ---------------------------------------------------
__device__ __forceinline__ uint32_t f2tf32(float f) {
    uint32_t r;
    asm("cvt.rna.tf32.f32 %0, %1;" : "=r"(r) : "f"(f));
    return r;
}
__device__ __forceinline__ float tf32f(float f) {
    return __uint_as_float(f2tf32(f));
}
__device__ __forceinline__ float ex2(float x) {
    float r;
    asm("ex2.approx.f32 %0, %1;" : "=f"(r) : "f"(x));
    return r;
}
__device__ __forceinline__ uint32_t smem_u32(const void* p) {
    uint32_t a;
    asm("{ .reg .u64 t; cvta.to.shared.u64 t, %1; cvt.u32.u64 %0, t; }"
        : "=r"(a) : "l"(p));
    return a;
}
__device__ __forceinline__ void cp16(uint32_t saddr, const void* g) {
    asm volatile("cp.async.ca.shared.global [%0], [%1], 16;"
                 :: "r"(saddr), "l"(g));
}
#define CP_COMMIT() asm volatile("cp.async.commit_group;" ::: "memory")
#define CP_WAIT1()  asm volatile("cp.async.wait_group 1;" ::: "memory")
#define CP_WAIT0()  asm volatile("cp.async.wait_group 0;" ::: "memory")

__device__ __forceinline__ void mma_tf32(float c[4], const uint32_t a[4],
                                         const uint32_t b[2]) {
    asm volatile(
        "mma.sync.aligned.m16n8k8.row.col.f32.tf32.tf32.f32 "
        "{%0,%1,%2,%3}, {%4,%5,%6,%7}, {%8,%9}, {%0,%1,%2,%3};"
        : "+f"(c[0]), "+f"(c[1]), "+f"(c[2]), "+f"(c[3])
        : "r"(a[0]), "r"(a[1]), "r"(a[2]), "r"(a[3]), "r"(b[0]), "r"(b[1]));
}

// ---------------- weight transpose: g_WT[z][n][k] = tf32(W_z[k][n]) ----------
__global__ void __launch_bounds__(256) transpose_kernel(
    const float* __restrict__ Wq, const float* __restrict__ Wk,
    const float* __restrict__ Wv, const float* __restrict__ Wo)
{
    __shared__ float t[32][33];
    const float* src = (blockIdx.z == 0) ? Wq : (blockIdx.z == 1) ? Wk
                     : (blockIdx.z == 2) ? Wv : Wo;
    float* dst = g_WT + (size_t)blockIdx.z * ND * ND;
    int x0 = blockIdx.x * 32, y0 = blockIdx.y * 32;
    int tx = threadIdx.x, ty = threadIdx.y;          // 32 x 8
    #pragma unroll
    for (int j = 0; j < 32; j += 8)
        t[ty + j][tx] = src[(size_t)(y0 + ty + j) * ND + x0 + tx];
    __syncthreads();
    #pragma unroll
    for (int j = 0; j < 32; j += 8)
        dst[(size_t)(x0 + ty + j) * ND + y0 + tx] = tf32f(t[tx][ty + j]);
}

// ---------------- gather (tf32 outputs) -------------------------------------
__global__ void __launch_bounds__(256) gather_kernel(
    const float* __restrict__ x,
    const int*   __restrict__ pq,
    const int*   __restrict__ pk)
{
    int b  = blockIdx.y;
    int i4 = (blockIdx.x * 256 + threadIdx.x) * 4;
    const float* xb = x + (size_t)b * LD;

    int q0 = pq[i4+0], q1 = pq[i4+1], q2 = pq[i4+2], q3 = pq[i4+3];
    int k0 = pk[i4+0], k1 = pk[i4+1], k2 = pk[i4+2], k3 = pk[i4+3];

    uint4 vq = make_uint4(f2tf32(xb[q0]), f2tf32(xb[q1]),
                          f2tf32(xb[q2]), f2tf32(xb[q3]));
    uint4 vk = make_uint4(f2tf32(xb[k0]), f2tf32(xb[k1]),
                          f2tf32(xb[k2]), f2tf32(xb[k3]));
    float4 vx = *(const float4*)&xb[i4];
    uint4 uv = make_uint4(f2tf32(vx.x), f2tf32(vx.y), f2tf32(vx.z), f2tf32(vx.w));

    *(uint4*)&g_xq[(size_t)b*LD + i4] = vq;
    *(uint4*)&g_xk[(size_t)b*LD + i4] = vk;
    *(uint4*)&g_xv[(size_t)b*LD + i4] = uv;
}

// ---------------- tf32 GEMM (cp.async double-buffered, 256 thr) --------------
// A and BT hold tf32 bit patterns already.
#define AS_STRIDE 36
#define TILE_WORDS (128*AS_STRIDE)
#define GEMM_SMEM (4*TILE_WORDS*4)      // 73728 B

__device__ __forceinline__ void gemm_core(
    const float* __restrict__ A,
    const float* __restrict__ BT,
    float*       __restrict__ C,
    const float* __restrict__ bias,
    int mode, float osc)
{
    extern __shared__ uint32_t smg[];
    uint32_t sA = smem_u32(smg);
    uint32_t sB = sA + 2*TILE_WORDS*4;

    int tid  = threadIdx.x;
    int lane = tid & 31, wid = tid >> 5;
    int wm = wid >> 1, wn = wid & 1;          // 4 x 2 warps
    int g = lane >> 2, t = lane & 3;
    int m0 = blockIdx.y * 128, n0 = blockIdx.x * 128;
    int lr = tid >> 3;          // 0..31
    int lc = tid & 7;           // 0..7

    float c[2][8][4];
    #pragma unroll
    for (int mt = 0; mt < 2; mt++)
        #pragma unroll
        for (int nt = 0; nt < 8; nt++)
            #pragma unroll
            for (int i = 0; i < 4; i++) c[mt][nt][i] = 0.f;

    // issue k-tile kt into stage st  (128 rows x 32 words per operand)
    auto issue = [&](int kt, int st) {
        #pragma unroll
        for (int it = 0; it < 4; it++) {
            int r = it * 32 + lr;
            cp16(sA + (st*TILE_WORDS + r*AS_STRIDE + lc*4)*4,
                 &A[(size_t)(m0 + r) * ND + kt*32 + lc*4]);
            cp16(sB + (st*TILE_WORDS + r*AS_STRIDE + lc*4)*4,
                 &BT[(size_t)(n0 + r) * ND + kt*32 + lc*4]);
        }
    };

    issue(0, 0);
    CP_COMMIT();

    for (int kt = 0; kt < 24; kt++) {
        int st = kt & 1;
        if (kt < 23) { issue(kt + 1, st ^ 1); CP_COMMIT(); CP_WAIT1(); }
        else         { CP_WAIT0(); }
        __syncthreads();

        const uint32_t* As = smg + st * TILE_WORDS;
        const uint32_t* Bs = smg + 2*TILE_WORDS + st * TILE_WORDS;
        #pragma unroll
        for (int kk = 0; kk < 4; kk++) {
            int k0 = kk * 8 + t;
            uint32_t a[2][4], b[8][2];
            #pragma unroll
            for (int mt = 0; mt < 2; mt++) {
                int mr = wm * 32 + mt * 16 + g;
                a[mt][0] = As[mr * AS_STRIDE + k0];
                a[mt][1] = As[(mr + 8) * AS_STRIDE + k0];
                a[mt][2] = As[mr * AS_STRIDE + k0 + 4];
                a[mt][3] = As[(mr + 8) * AS_STRIDE + k0 + 4];
            }
            #pragma unroll
            for (int nt = 0; nt < 8; nt++) {
                int nr = wn * 64 + nt * 8 + g;
                b[nt][0] = Bs[nr * AS_STRIDE + k0];
                b[nt][1] = Bs[nr * AS_STRIDE + k0 + 4];
            }
            #pragma unroll
            for (int mt = 0; mt < 2; mt++)
                #pragma unroll
                for (int nt = 0; nt < 8; nt++)
                    mma_tf32(c[mt][nt], a[mt], b[nt]);
        }
        __syncthreads();
    }

    // epilogue
    #pragma unroll
    for (int mt = 0; mt < 2; mt++) {
        int m = m0 + wm * 32 + mt * 16 + g;
        #pragma unroll
        for (int nt = 0; nt < 8; nt++) {
            int n = n0 + wn * 64 + nt * 8 + 2 * t;
            if (mode == 0) {
                int b0i = m >> 10, l = m & 1023;
                int h = n >> 6, dh = n & 63;
                size_t base0 = ((((size_t)b0i * NH + h) * NL + l) << 6) + dh;
                *(float2*)&C[base0] = make_float2(
                    tf32f(c[mt][nt][0]*osc), tf32f(c[mt][nt][1]*osc));
                size_t base2 = ((((size_t)b0i * NH + h) * NL + (l + 8)) << 6) + dh;
                *(float2*)&C[base2] = make_float2(
                    tf32f(c[mt][nt][2]*osc), tf32f(c[mt][nt][3]*osc));
            } else if (mode == 2) {
                int b0i = m >> 10, l = m & 1023;
                int h = n >> 6, dh = n & 63;
                size_t base = (((size_t)b0i * NH + h) * NDH + dh) * NL + l;
                C[base]          = tf32f(c[mt][nt][0]);
                C[base + NL]     = tf32f(c[mt][nt][1]);
                C[base + 8]      = tf32f(c[mt][nt][2]);
                C[base + NL + 8] = tf32f(c[mt][nt][3]);
            } else {
                float2 bb = *(const float2*)&bias[n];
                *(float2*)&C[(size_t)m * ND + n] =
                    make_float2(c[mt][nt][0] + bb.x, c[mt][nt][1] + bb.y);
                *(float2*)&C[(size_t)(m + 8) * ND + n] =
                    make_float2(c[mt][nt][2] + bb.x, c[mt][nt][3] + bb.y);
            }
        }
    }
}

// fused q/k/v projections: blockIdx.z selects which GEMM
__global__ void __launch_bounds__(256) qkv_kernel()
{
    int z = blockIdx.z;
    const float* A  = (z == 0) ? g_xq : (z == 1) ? g_xk : g_xv;
    const float* BT = g_WT + (size_t)z * ND * ND;
    float* C        = (z == 0) ? g_q : (z == 1) ? g_k : g_v;
    float osc       = (z == 0) ? SC_Q : 1.0f;
    gemm_core(A, BT, C, nullptr, (z == 2) ? 2 : 0, osc);
}

// final projection + bias
__global__ void __launch_bounds__(256) proj_kernel(
    const float* __restrict__ bias, float* __restrict__ out)
{
    gemm_core(g_o, g_WT + 3 * (size_t)ND * ND, out, bias, 1, 1.0f);
}

// ---------------- tensor-core flash attention (tf32, cp.async) --------------
// grid (8 q-tiles of 128, 192 bh), block 128 (4 warps, warp = 32 q-rows).
#define ASTR2 68
#define KV_WORDS (64*ASTR2)                       // 4352 words per stage
#define ATTN_SMEM ((4*KV_WORDS + 128*ASTR2) * 4)  // 104448 B

__global__ void __launch_bounds__(128) attn_mma_kernel()
{
    extern __shared__ uint32_t smu[];
    uint32_t sb = smem_u32(smu);
    uint32_t (*Ps)[ASTR2] = (uint32_t(*)[ASTR2])(smu + 4*KV_WORDS);

    int tid = threadIdx.x, lane = tid & 31, wid = tid >> 5;
    int g = lane >> 2, t = lane & 3;
    int bh = blockIdx.y, qt = blockIdx.x;

    const float* Qg  = g_q + (size_t)bh * NL * NDH + (size_t)qt * 128 * NDH;
    const float* Kg  = g_k + (size_t)bh * NL * NDH;
    const float* VTg = g_v + (size_t)bh * NDH * NL;

    // issue K/V tile kt into stage st  (full 64 rows x 64 cols each)
    auto issue_kv = [&](int kt, int st) {
        const float* Kt = Kg + (size_t)kt * 64 * 64;
        #pragma unroll
        for (int it = 0; it < 8; it++) {
            int idx = it * 128 + tid;          // 0..1023
            int r = idx >> 4, c4 = (idx & 15) << 2;   // r 0..63, c4 0..60
            cp16(sb + (st*KV_WORDS + r*ASTR2 + c4)*4, &Kt[r * 64 + c4]);
            cp16(sb + ((2 + st)*KV_WORDS + r*ASTR2 + c4)*4,
                 &VTg[(size_t)r * NL + kt * 64 + c4]);
        }
    };

    issue_kv(0, 0);
    CP_COMMIT();

    // stage Q (128 x 64, tf32 bits) into Ps
    #pragma unroll
    for (int it = 0; it < 16; it++) {
        int idx = it * 128 + tid;
        int r = idx >> 4, c4 = (idx & 15) << 2;
        *(uint4*)&Ps[r][c4] = *(const uint4*)&Qg[r * 64 + c4];
    }
    __syncthreads();

    uint32_t aq[2][8][4];
    #pragma unroll
    for (int h = 0; h < 2; h++) {
        int mr = wid * 32 + h * 16 + g;
        #pragma unroll
        for (int kk = 0; kk < 8; kk++) {
            aq[h][kk][0] = Ps[mr][kk*8 + t];
            aq[h][kk][1] = Ps[mr + 8][kk*8 + t];
            aq[h][kk][2] = Ps[mr][kk*8 + t + 4];
            aq[h][kk][3] = Ps[mr + 8][kk*8 + t + 4];
        }
    }

    float mI[2][2], lI[2][2];
    #pragma unroll
    for (int h = 0; h < 2; h++) { mI[h][0] = mI[h][1] = -1e30f; lI[h][0] = lI[h][1] = 0.f; }
    float o[2][8][4];
    #pragma unroll
    for (int h = 0; h < 2; h++)
        #pragma unroll
        for (int nt = 0; nt < 8; nt++)
            #pragma unroll
            for (int i = 0; i < 4; i++) o[h][nt][i] = 0.f;

    for (int kt = 0; kt < 16; kt++) {
        int st = kt & 1;
        if (kt < 15) { issue_kv(kt + 1, st ^ 1); CP_COMMIT(); CP_WAIT1(); }
        else         { CP_WAIT0(); }
        __syncthreads();

        uint32_t (*Ks)[ASTR2] = (uint32_t(*)[ASTR2])(smu + st*KV_WORDS);
        uint32_t (*Vs)[ASTR2] = (uint32_t(*)[ASTR2])(smu + (2 + st)*KV_WORDS);

        #pragma unroll
        for (int h = 0; h < 2; h++) {
            int mr = wid * 32 + h * 16 + g;
            float s[8][4];
            #pragma unroll
            for (int nt = 0; nt < 8; nt++)
                #pragma unroll
                for (int i = 0; i < 4; i++) s[nt][i] = 0.f;
            #pragma unroll
            for (int kk = 0; kk < 8; kk++) {
                #pragma unroll
                for (int nt = 0; nt < 8; nt++) {
                    uint32_t b[2];
                    int nr = nt * 8 + g;
                    b[0] = Ks[nr][kk*8 + t];
                    b[1] = Ks[nr][kk*8 + t + 4];
                    mma_tf32(s[nt], aq[h][kk], b);
                }
            }
            // online softmax (log2 domain, scale folded into Q)
            float mx0 = -1e30f, mx1 = -1e30f;
            #pragma unroll
            for (int nt = 0; nt < 8; nt++) {
                mx0 = fmaxf(mx0, fmaxf(s[nt][0], s[nt][1]));
                mx1 = fmaxf(mx1, fmaxf(s[nt][2], s[nt][3]));
            }
            mx0 = fmaxf(mx0, __shfl_xor_sync(0xffffffffu, mx0, 1));
            mx0 = fmaxf(mx0, __shfl_xor_sync(0xffffffffu, mx0, 2));
            mx1 = fmaxf(mx1, __shfl_xor_sync(0xffffffffu, mx1, 1));
            mx1 = fmaxf(mx1, __shfl_xor_sync(0xffffffffu, mx1, 2));

            float mn0 = fmaxf(mI[h][0], mx0), mn1 = fmaxf(mI[h][1], mx1);
            float corr0 = ex2(mI[h][0] - mn0), corr1 = ex2(mI[h][1] - mn1);
            mI[h][0] = mn0; mI[h][1] = mn1;

            float sum0 = 0.f, sum1 = 0.f;
            #pragma unroll
            for (int nt = 0; nt < 8; nt++) {
                float p0 = ex2(s[nt][0] - mn0);
                float p1 = ex2(s[nt][1] - mn0);
                float p2 = ex2(s[nt][2] - mn1);
                float p3 = ex2(s[nt][3] - mn1);
                sum0 += p0 + p1; sum1 += p2 + p3;
                int col = nt * 8 + 2 * t;
                *(uint2*)&Ps[mr][col]     = make_uint2(f2tf32(p0), f2tf32(p1));
                *(uint2*)&Ps[mr + 8][col] = make_uint2(f2tf32(p2), f2tf32(p3));
            }
            sum0 += __shfl_xor_sync(0xffffffffu, sum0, 1);
            sum0 += __shfl_xor_sync(0xffffffffu, sum0, 2);
            sum1 += __shfl_xor_sync(0xffffffffu, sum1, 1);
            sum1 += __shfl_xor_sync(0xffffffffu, sum1, 2);
            lI[h][0] = lI[h][0] * corr0 + sum0;
            lI[h][1] = lI[h][1] * corr1 + sum1;

            #pragma unroll
            for (int nt = 0; nt < 8; nt++) {
                o[h][nt][0] *= corr0; o[h][nt][1] *= corr0;
                o[h][nt][2] *= corr1; o[h][nt][3] *= corr1;
            }
        }
        __syncwarp();

        // O += P @ V : V b-fragments shared across both halves
        #pragma unroll
        for (int kk = 0; kk < 8; kk++) {
            uint32_t vb[8][2];
            #pragma unroll
            for (int nt = 0; nt < 8; nt++) {
                int nr = nt * 8 + g;
                vb[nt][0] = Vs[nr][kk*8 + t];
                vb[nt][1] = Vs[nr][kk*8 + t + 4];
            }
            #pragma unroll
            for (int h = 0; h < 2; h++) {
                int mr = wid * 32 + h * 16 + g;
                uint32_t ap[4];
                ap[0] = Ps[mr][kk*8 + t];
                ap[1] = Ps[mr + 8][kk*8 + t];
                ap[2] = Ps[mr][kk*8 + t + 4];
                ap[3] = Ps[mr + 8][kk*8 + t + 4];
                #pragma unroll
                for (int nt = 0; nt < 8; nt++)
                    mma_tf32(o[h][nt], ap, vb[nt]);
            }
        }
        __syncthreads();
    }

    // epilogue (tf32 bits; proj gemm consumes directly)
    int bb = bh / NH, hh = bh % NH;
    float* Og = g_o + ((size_t)bb * NL + qt * 128) * ND + hh * 64;
    #pragma unroll
    for (int h = 0; h < 2; h++) {
        float inv0 = 1.f / lI[h][0], inv1 = 1.f / lI[h][1];
        int mr = wid * 32 + h * 16 + g;
        #pragma unroll
        for (int nt = 0; nt < 8; nt++) {
            int col = nt * 8 + 2 * t;
            *(float2*)&Og[(size_t)mr * ND + col] = make_float2(
                tf32f(o[h][nt][0] * inv0), tf32f(o[h][nt][1] * inv0));
            *(float2*)&Og[(size_t)(mr + 8) * ND + col] = make_float2(
                tf32f(o[h][nt][2] * inv1), tf32f(o[h][nt][3] * inv1));
        }
    }
}

// ---------------- launch -----------------------------------------------------
extern "C" void kernel_launch(void* const* d_in, const int* in_sizes, int n_in,
                              void* d_out, int out_size)
{
    const float* x  = (const float*)d_in[0];
    const float* Wq = (const float*)d_in[1];
    const float* Wk = (const float*)d_in[2];
    const float* Wv = (const float*)d_in[3];
    const float* Wo = (const float*)d_in[4];
    const float* bo = (const float*)d_in[5];
    const int*   pq = (const int*)d_in[6];
    const int*   pk = (const int*)d_in[7];
    float* out = (float*)d_out;

    cudaFuncSetAttribute(attn_mma_kernel,
                         cudaFuncAttributeMaxDynamicSharedMemorySize, ATTN_SMEM);
    cudaFuncSetAttribute(qkv_kernel,
                         cudaFuncAttributeMaxDynamicSharedMemorySize, GEMM_SMEM);
    cudaFuncSetAttribute(proj_kernel,
                         cudaFuncAttributeMaxDynamicSharedMemorySize, GEMM_SMEM);

    // 0. weight transposes (tf32 bits)
    transpose_kernel<<<dim3(24, 24, 4), dim3(32, 8)>>>(Wq, Wk, Wv, Wo);

    // 1. gathers (tf32 bits) + linear x copy
    gather_kernel<<<dim3(LD / 1024, NB), 256>>>(x, pq, pk);

    // 2. fused q/k/v projections (cp.async pipelined tf32 mma)
    qkv_kernel<<<dim3(ND / 128, NM / 128, 3), 256, GEMM_SMEM>>>();

    // 3. attention (tensor-core flash, cp.async double-buffered K/V)
    attn_mma_kernel<<<dim3(NL / 128, NB * NH), 128, ATTN_SMEM>>>();

    // 4. output projection + bias
    proj_kernel<<<dim3(ND / 128, NM / 128), 256, GEMM_SMEM>>>(bo, out);
}

// round 9
// speedup vs baseline: 3.5643x; 1.0714x over previous
#include <cuda_runtime.h>
#include <cstdint>

#define NB 16
#define NL 1024
#define ND 768
#define NH 12
#define NDH 64
#define LD (NL*ND)          // 786432
#define NM (NB*NL)          // 16384

// ---------------- scratch (static device globals; no allocation) ----------
__device__ float g_xT[NB*LD];            // x transposed: [i][b], tf32 bits
__device__ float g_xq[NB*LD];            // gathered q input, tf32 bits
__device__ float g_xk[NB*LD];            // gathered k input, tf32 bits
__device__ float g_xv[NB*LD];            // x copy, tf32 bits
__device__ float g_q [NM*ND];            // (b,h,l,dh), tf32 bits, pre-scaled
__device__ float g_k [NM*ND];            // (b,h,l,dh), tf32 bits
__device__ float g_v [NM*ND];            // V^T: (b,h,dh,l), tf32 bits
__device__ float g_o [NM*ND];            // attention output, tf32 bits
__device__ float g_WT[4*ND*ND];          // transposed weights [n][k], tf32 bits

// 0.125 * log2(e)
#define SC_Q 0.18033688011112042f

// ---------------- helpers ---------------------------------------------------
__device__ __forceinline__ uint32_t f2tf32(float f) {
    uint32_t r;
    asm("cvt.rna.tf32.f32 %0, %1;" : "=r"(r) : "f"(f));
    return r;
}
__device__ __forceinline__ float tf32f(float f) {
    return __uint_as_float(f2tf32(f));
}
__device__ __forceinline__ float ex2(float x) {
    float r;
    asm("ex2.approx.f32 %0, %1;" : "=f"(r) : "f"(x));
    return r;
}
__device__ __forceinline__ uint32_t smem_u32(const void* p) {
    uint32_t a;
    asm("{ .reg .u64 t; cvta.to.shared.u64 t, %1; cvt.u32.u64 %0, t; }"
        : "=r"(a) : "l"(p));
    return a;
}
__device__ __forceinline__ void cp16(uint32_t saddr, const void* g) {
    asm volatile("cp.async.ca.shared.global [%0], [%1], 16;"
                 :: "r"(saddr), "l"(g));
}
#define CP_COMMIT() asm volatile("cp.async.commit_group;" ::: "memory")
#define CP_WAIT1()  asm volatile("cp.async.wait_group 1;" ::: "memory")
#define CP_WAIT0()  asm volatile("cp.async.wait_group 0;" ::: "memory")

__device__ __forceinline__ void mma_tf32(float c[4], const uint32_t a[4],
                                         const uint32_t b[2]) {
    asm volatile(
        "mma.sync.aligned.m16n8k8.row.col.f32.tf32.tf32.f32 "
        "{%0,%1,%2,%3}, {%4,%5,%6,%7}, {%8,%9}, {%0,%1,%2,%3};"
        : "+f"(c[0]), "+f"(c[1]), "+f"(c[2]), "+f"(c[3])
        : "r"(a[0]), "r"(a[1]), "r"(a[2]), "r"(a[3]), "r"(b[0]), "r"(b[1]));
}

// ---------------- weight transpose: g_WT[z][n][k] = tf32(W_z[k][n]) ----------
__global__ void __launch_bounds__(256) transpose_kernel(
    const float* __restrict__ Wq, const float* __restrict__ Wk,
    const float* __restrict__ Wv, const float* __restrict__ Wo)
{
    __shared__ float t[32][33];
    const float* src = (blockIdx.z == 0) ? Wq : (blockIdx.z == 1) ? Wk
                     : (blockIdx.z == 2) ? Wv : Wo;
    float* dst = g_WT + (size_t)blockIdx.z * ND * ND;
    int x0 = blockIdx.x * 32, y0 = blockIdx.y * 32;
    int tx = threadIdx.x, ty = threadIdx.y;          // 32 x 8
    #pragma unroll
    for (int j = 0; j < 32; j += 8)
        t[ty + j][tx] = src[(size_t)(y0 + ty + j) * ND + x0 + tx];
    __syncthreads();
    #pragma unroll
    for (int j = 0; j < 32; j += 8)
        dst[(size_t)(x0 + ty + j) * ND + y0 + tx] = tf32f(t[tx][ty + j]);
}

// ---------------- x transpose: g_xT[i][b] = tf32(x[b][i]); also g_xv --------
__global__ void __launch_bounds__(256) xt_kernel(const float* __restrict__ x)
{
    __shared__ uint32_t tile[64][17];
    int tid = threadIdx.x;
    int i0 = blockIdx.x * 64;

    #pragma unroll
    for (int p = 0; p < 4; p++) {
        int b = p * 4 + (tid >> 6);
        int i = tid & 63;
        uint32_t v = f2tf32(x[(size_t)b * LD + i0 + i]);
        tile[i][b] = v;
        g_xv[(size_t)b * LD + i0 + i] = __uint_as_float(v);
    }
    __syncthreads();
    #pragma unroll
    for (int p = 0; p < 4; p++) {
        int i = p * 16 + (tid >> 4);
        int b = tid & 15;
        g_xT[(size_t)(i0 + i) * 16 + b] = __uint_as_float(tile[i][b]);
    }
}

// ---------------- gather: one 64B xT line serves all 16 batches -------------
__global__ void __launch_bounds__(256) gather_kernel(
    const int* __restrict__ pq, const int* __restrict__ pk)
{
    int i = blockIdx.x * 256 + threadIdx.x;          // 0..786431
    const int* pp = blockIdx.y ? pk : pq;
    float* dst    = blockIdx.y ? g_xk : g_xq;
    int idx = pp[i];

    const float4* src = (const float4*)&g_xT[(size_t)idx * 16];
    float4 v0 = src[0], v1 = src[1], v2 = src[2], v3 = src[3];
    float vals[16] = {v0.x, v0.y, v0.z, v0.w, v1.x, v1.y, v1.z, v1.w,
                      v2.x, v2.y, v2.z, v2.w, v3.x, v3.y, v3.z, v3.w};
    #pragma unroll
    for (int b = 0; b < 16; b++)
        dst[(size_t)b * LD + i] = vals[b];
}

// ---------------- tf32 GEMM (cp.async double-buffered, 256 thr, occ 2) ------
#define AS_STRIDE 36
#define TILE_WORDS (128*AS_STRIDE)
#define GEMM_SMEM (4*TILE_WORDS*4)      // 73728 B

__device__ __forceinline__ void gemm_core(
    const float* __restrict__ A,
    const float* __restrict__ BT,
    float*       __restrict__ C,
    const float* __restrict__ bias,
    int mode, float osc)
{
    extern __shared__ uint32_t smg[];
    uint32_t sA = smem_u32(smg);
    uint32_t sB = sA + 2*TILE_WORDS*4;

    int tid  = threadIdx.x;
    int lane = tid & 31, wid = tid >> 5;
    int wm = wid >> 1, wn = wid & 1;          // 4 x 2 warps
    int g = lane >> 2, t = lane & 3;
    int m0 = blockIdx.y * 128, n0 = blockIdx.x * 128;
    int lr = tid >> 3;          // 0..31
    int lc = tid & 7;           // 0..7

    float c[2][8][4];
    #pragma unroll
    for (int mt = 0; mt < 2; mt++)
        #pragma unroll
        for (int nt = 0; nt < 8; nt++)
            #pragma unroll
            for (int i = 0; i < 4; i++) c[mt][nt][i] = 0.f;

    auto issue = [&](int kt, int st) {
        #pragma unroll
        for (int it = 0; it < 4; it++) {
            int r = it * 32 + lr;
            cp16(sA + (st*TILE_WORDS + r*AS_STRIDE + lc*4)*4,
                 &A[(size_t)(m0 + r) * ND + kt*32 + lc*4]);
            cp16(sB + (st*TILE_WORDS + r*AS_STRIDE + lc*4)*4,
                 &BT[(size_t)(n0 + r) * ND + kt*32 + lc*4]);
        }
    };

    issue(0, 0);
    CP_COMMIT();

    for (int kt = 0; kt < 24; kt++) {
        int st = kt & 1;
        if (kt < 23) { issue(kt + 1, st ^ 1); CP_COMMIT(); CP_WAIT1(); }
        else         { CP_WAIT0(); }
        __syncthreads();

        const uint32_t* As = smg + st * TILE_WORDS;
        const uint32_t* Bs = smg + 2*TILE_WORDS + st * TILE_WORDS;
        #pragma unroll
        for (int kk = 0; kk < 4; kk++) {
            int k0 = kk * 8 + t;
            uint32_t a[2][4], b[8][2];
            #pragma unroll
            for (int mt = 0; mt < 2; mt++) {
                int mr = wm * 32 + mt * 16 + g;
                a[mt][0] = As[mr * AS_STRIDE + k0];
                a[mt][1] = As[(mr + 8) * AS_STRIDE + k0];
                a[mt][2] = As[mr * AS_STRIDE + k0 + 4];
                a[mt][3] = As[(mr + 8) * AS_STRIDE + k0 + 4];
            }
            #pragma unroll
            for (int nt = 0; nt < 8; nt++) {
                int nr = wn * 64 + nt * 8 + g;
                b[nt][0] = Bs[nr * AS_STRIDE + k0];
                b[nt][1] = Bs[nr * AS_STRIDE + k0 + 4];
            }
            #pragma unroll
            for (int mt = 0; mt < 2; mt++)
                #pragma unroll
                for (int nt = 0; nt < 8; nt++)
                    mma_tf32(c[mt][nt], a[mt], b[nt]);
        }
        __syncthreads();
    }

    // epilogue
    #pragma unroll
    for (int mt = 0; mt < 2; mt++) {
        int m = m0 + wm * 32 + mt * 16 + g;
        #pragma unroll
        for (int nt = 0; nt < 8; nt++) {
            int n = n0 + wn * 64 + nt * 8 + 2 * t;
            if (mode == 0) {
                int b0i = m >> 10, l = m & 1023;
                int h = n >> 6, dh = n & 63;
                size_t base0 = ((((size_t)b0i * NH + h) * NL + l) << 6) + dh;
                *(float2*)&C[base0] = make_float2(
                    tf32f(c[mt][nt][0]*osc), tf32f(c[mt][nt][1]*osc));
                size_t base2 = ((((size_t)b0i * NH + h) * NL + (l + 8)) << 6) + dh;
                *(float2*)&C[base2] = make_float2(
                    tf32f(c[mt][nt][2]*osc), tf32f(c[mt][nt][3]*osc));
            } else if (mode == 2) {
                int b0i = m >> 10, l = m & 1023;
                int h = n >> 6, dh = n & 63;
                size_t base = (((size_t)b0i * NH + h) * NDH + dh) * NL + l;
                C[base]          = tf32f(c[mt][nt][0]);
                C[base + NL]     = tf32f(c[mt][nt][1]);
                C[base + 8]      = tf32f(c[mt][nt][2]);
                C[base + NL + 8] = tf32f(c[mt][nt][3]);
            } else {
                float2 bb = *(const float2*)&bias[n];
                *(float2*)&C[(size_t)m * ND + n] =
                    make_float2(c[mt][nt][0] + bb.x, c[mt][nt][1] + bb.y);
                *(float2*)&C[(size_t)(m + 8) * ND + n] =
                    make_float2(c[mt][nt][2] + bb.x, c[mt][nt][3] + bb.y);
            }
        }
    }
}

// fused q/k/v projections: blockIdx.z selects which GEMM
__global__ void __launch_bounds__(256, 2) qkv_kernel()
{
    int z = blockIdx.z;
    const float* A  = (z == 0) ? g_xq : (z == 1) ? g_xk : g_xv;
    const float* BT = g_WT + (size_t)z * ND * ND;
    float* C        = (z == 0) ? g_q : (z == 1) ? g_k : g_v;
    float osc       = (z == 0) ? SC_Q : 1.0f;
    gemm_core(A, BT, C, nullptr, (z == 2) ? 2 : 0, osc);
}

// final projection + bias
__global__ void __launch_bounds__(256, 2) proj_kernel(
    const float* __restrict__ bias, float* __restrict__ out)
{
    gemm_core(g_o, g_WT + 3 * (size_t)ND * ND, out, bias, 1, 1.0f);
}

// ---------------- tensor-core flash attention (tf32, cp.async) --------------
// grid (8 q-tiles of 128, 192 bh), block 128 (4 warps, warp = 32 q-rows).
#define ASTR2 68
#define KV_WORDS (64*ASTR2)                       // 4352 words per stage
#define ATTN_SMEM ((4*KV_WORDS + 128*ASTR2) * 4)  // 104448 B

__global__ void __launch_bounds__(128) attn_mma_kernel()
{
    extern __shared__ uint32_t smu[];
    uint32_t sb = smem_u32(smu);
    uint32_t (*Ps)[ASTR2] = (uint32_t(*)[ASTR2])(smu + 4*KV_WORDS);

    int tid = threadIdx.x, lane = tid & 31, wid = tid >> 5;
    int g = lane >> 2, t = lane & 3;
    int bh = blockIdx.y, qt = blockIdx.x;

    const float* Qg  = g_q + (size_t)bh * NL * NDH + (size_t)qt * 128 * NDH;
    const float* Kg  = g_k + (size_t)bh * NL * NDH;
    const float* VTg = g_v + (size_t)bh * NDH * NL;

    auto issue_kv = [&](int kt, int st) {
        const float* Kt = Kg + (size_t)kt * 64 * 64;
        #pragma unroll
        for (int it = 0; it < 8; it++) {
            int idx = it * 128 + tid;          // 0..1023
            int r = idx >> 4, c4 = (idx & 15) << 2;
            cp16(sb + (st*KV_WORDS + r*ASTR2 + c4)*4, &Kt[r * 64 + c4]);
            cp16(sb + ((2 + st)*KV_WORDS + r*ASTR2 + c4)*4,
                 &VTg[(size_t)r * NL + kt * 64 + c4]);
        }
    };

    issue_kv(0, 0);
    CP_COMMIT();

    #pragma unroll
    for (int it = 0; it < 16; it++) {
        int idx = it * 128 + tid;
        int r = idx >> 4, c4 = (idx & 15) << 2;
        *(uint4*)&Ps[r][c4] = *(const uint4*)&Qg[r * 64 + c4];
    }
    __syncthreads();

    uint32_t aq[2][8][4];
    #pragma unroll
    for (int h = 0; h < 2; h++) {
        int mr = wid * 32 + h * 16 + g;
        #pragma unroll
        for (int kk = 0; kk < 8; kk++) {
            aq[h][kk][0] = Ps[mr][kk*8 + t];
            aq[h][kk][1] = Ps[mr + 8][kk*8 + t];
            aq[h][kk][2] = Ps[mr][kk*8 + t + 4];
            aq[h][kk][3] = Ps[mr + 8][kk*8 + t + 4];
        }
    }

    float mI[2][2], lI[2][2];
    #pragma unroll
    for (int h = 0; h < 2; h++) { mI[h][0] = mI[h][1] = -1e30f; lI[h][0] = lI[h][1] = 0.f; }
    float o[2][8][4];
    #pragma unroll
    for (int h = 0; h < 2; h++)
        #pragma unroll
        for (int nt = 0; nt < 8; nt++)
            #pragma unroll
            for (int i = 0; i < 4; i++) o[h][nt][i] = 0.f;

    for (int kt = 0; kt < 16; kt++) {
        int st = kt & 1;
        if (kt < 15) { issue_kv(kt + 1, st ^ 1); CP_COMMIT(); CP_WAIT1(); }
        else         { CP_WAIT0(); }
        __syncthreads();

        uint32_t (*Ks)[ASTR2] = (uint32_t(*)[ASTR2])(smu + st*KV_WORDS);
        uint32_t (*Vs)[ASTR2] = (uint32_t(*)[ASTR2])(smu + (2 + st)*KV_WORDS);

        #pragma unroll
        for (int h = 0; h < 2; h++) {
            int mr = wid * 32 + h * 16 + g;
            float s[8][4];
            #pragma unroll
            for (int nt = 0; nt < 8; nt++)
                #pragma unroll
                for (int i = 0; i < 4; i++) s[nt][i] = 0.f;
            #pragma unroll
            for (int kk = 0; kk < 8; kk++) {
                #pragma unroll
                for (int nt = 0; nt < 8; nt++) {
                    uint32_t b[2];
                    int nr = nt * 8 + g;
                    b[0] = Ks[nr][kk*8 + t];
                    b[1] = Ks[nr][kk*8 + t + 4];
                    mma_tf32(s[nt], aq[h][kk], b);
                }
            }
            float mx0 = -1e30f, mx1 = -1e30f;
            #pragma unroll
            for (int nt = 0; nt < 8; nt++) {
                mx0 = fmaxf(mx0, fmaxf(s[nt][0], s[nt][1]));
                mx1 = fmaxf(mx1, fmaxf(s[nt][2], s[nt][3]));
            }
            mx0 = fmaxf(mx0, __shfl_xor_sync(0xffffffffu, mx0, 1));
            mx0 = fmaxf(mx0, __shfl_xor_sync(0xffffffffu, mx0, 2));
            mx1 = fmaxf(mx1, __shfl_xor_sync(0xffffffffu, mx1, 1));
            mx1 = fmaxf(mx1, __shfl_xor_sync(0xffffffffu, mx1, 2));

            float mn0 = fmaxf(mI[h][0], mx0), mn1 = fmaxf(mI[h][1], mx1);
            float corr0 = ex2(mI[h][0] - mn0), corr1 = ex2(mI[h][1] - mn1);
            mI[h][0] = mn0; mI[h][1] = mn1;

            float sum0 = 0.f, sum1 = 0.f;
            #pragma unroll
            for (int nt = 0; nt < 8; nt++) {
                float p0 = ex2(s[nt][0] - mn0);
                float p1 = ex2(s[nt][1] - mn0);
                float p2 = ex2(s[nt][2] - mn1);
                float p3 = ex2(s[nt][3] - mn1);
                sum0 += p0 + p1; sum1 += p2 + p3;
                int col = nt * 8 + 2 * t;
                *(uint2*)&Ps[mr][col]     = make_uint2(f2tf32(p0), f2tf32(p1));
                *(uint2*)&Ps[mr + 8][col] = make_uint2(f2tf32(p2), f2tf32(p3));
            }
            sum0 += __shfl_xor_sync(0xffffffffu, sum0, 1);
            sum0 += __shfl_xor_sync(0xffffffffu, sum0, 2);
            sum1 += __shfl_xor_sync(0xffffffffu, sum1, 1);
            sum1 += __shfl_xor_sync(0xffffffffu, sum1, 2);
            lI[h][0] = lI[h][0] * corr0 + sum0;
            lI[h][1] = lI[h][1] * corr1 + sum1;

            #pragma unroll
            for (int nt = 0; nt < 8; nt++) {
                o[h][nt][0] *= corr0; o[h][nt][1] *= corr0;
                o[h][nt][2] *= corr1; o[h][nt][3] *= corr1;
            }
        }
        __syncwarp();

        #pragma unroll
        for (int kk = 0; kk < 8; kk++) {
            uint32_t vb[8][2];
            #pragma unroll
            for (int nt = 0; nt < 8; nt++) {
                int nr = nt * 8 + g;
                vb[nt][0] = Vs[nr][kk*8 + t];
                vb[nt][1] = Vs[nr][kk*8 + t + 4];
            }
            #pragma unroll
            for (int h = 0; h < 2; h++) {
                int mr = wid * 32 + h * 16 + g;
                uint32_t ap[4];
                ap[0] = Ps[mr][kk*8 + t];
                ap[1] = Ps[mr + 8][kk*8 + t];
                ap[2] = Ps[mr][kk*8 + t + 4];
                ap[3] = Ps[mr + 8][kk*8 + t + 4];
                #pragma unroll
                for (int nt = 0; nt < 8; nt++)
                    mma_tf32(o[h][nt], ap, vb[nt]);
            }
        }
        __syncthreads();
    }

    int bb = bh / NH, hh = bh % NH;
    float* Og = g_o + ((size_t)bb * NL + qt * 128) * ND + hh * 64;
    #pragma unroll
    for (int h = 0; h < 2; h++) {
        float inv0 = 1.f / lI[h][0], inv1 = 1.f / lI[h][1];
        int mr = wid * 32 + h * 16 + g;
        #pragma unroll
        for (int nt = 0; nt < 8; nt++) {
            int col = nt * 8 + 2 * t;
            *(float2*)&Og[(size_t)mr * ND + col] = make_float2(
                tf32f(o[h][nt][0] * inv0), tf32f(o[h][nt][1] * inv0));
            *(float2*)&Og[(size_t)(mr + 8) * ND + col] = make_float2(
                tf32f(o[h][nt][2] * inv1), tf32f(o[h][nt][3] * inv1));
        }
    }
}

// ---------------- launch -----------------------------------------------------
extern "C" void kernel_launch(void* const* d_in, const int* in_sizes, int n_in,
                              void* d_out, int out_size)
{
    const float* x  = (const float*)d_in[0];
    const float* Wq = (const float*)d_in[1];
    const float* Wk = (const float*)d_in[2];
    const float* Wv = (const float*)d_in[3];
    const float* Wo = (const float*)d_in[4];
    const float* bo = (const float*)d_in[5];
    const int*   pq = (const int*)d_in[6];
    const int*   pk = (const int*)d_in[7];
    float* out = (float*)d_out;

    cudaFuncSetAttribute(attn_mma_kernel,
                         cudaFuncAttributeMaxDynamicSharedMemorySize, ATTN_SMEM);
    cudaFuncSetAttribute(qkv_kernel,
                         cudaFuncAttributeMaxDynamicSharedMemorySize, GEMM_SMEM);
    cudaFuncSetAttribute(proj_kernel,
                         cudaFuncAttributeMaxDynamicSharedMemorySize, GEMM_SMEM);

    // 0. weight transposes (tf32 bits) + x transpose (xT + xv)
    transpose_kernel<<<dim3(24, 24, 4), dim3(32, 8)>>>(Wq, Wk, Wv, Wo);
    xt_kernel<<<LD / 64, 256>>>(x);

    // 1. gathers: 64B xT line per index serves all 16 batches
    gather_kernel<<<dim3(LD / 256, 2), 256>>>(pq, pk);

    // 2. fused q/k/v projections (cp.async pipelined tf32 mma, occ 2)
    qkv_kernel<<<dim3(ND / 128, NM / 128, 3), 256, GEMM_SMEM>>>();

    // 3. attention (tensor-core flash, cp.async double-buffered K/V)
    attn_mma_kernel<<<dim3(NL / 128, NB * NH), 128, ATTN_SMEM>>>();

    // 4. output projection + bias
    proj_kernel<<<dim3(ND / 128, NM / 128), 256, GEMM_SMEM>>>(bo, out);
}